// round 12
// baseline (speedup 1.0000x reference)
#include <cuda_runtime.h>
#include <math.h>

#define Bb 32
#define Nn 325
#define Ee 64
#define St 12
#define NHOP 3
#define NNODE (Bb*Nn)        // 10400
#define BNE (Bb*Nn*Ee)       // 665600
#define SCALE_INV 0.125f
#define FRAG_PER_BC 2048     // 8 groups * 8 k8 * 32 lanes
#define FRAG_PER_HOP (Bb*6*FRAG_PER_BC)

// ---------------- scratch (device globals; no allocation allowed) ----------------
__device__ float d_adp[Nn*Nn];
__device__ float d_keysw[NHOP*BNE];
__device__ float d_base [NHOP*BNE];
__device__ float d_t6 [NHOP*6*BNE];
__device__ float d_t3b[NHOP*3*BNE];
__device__ float d_yp [NHOP*3*BNE];
__device__ float2 d_Kf2[NHOP*FRAG_PER_HOP];
__device__ float2 d_Vf2[NHOP*FRAG_PER_HOP];
__device__ float d_h[BNE], d_u[BNE], d_opre[BNE];
__device__ float d_prev[NNODE], d_sent[NNODE], d_acc[NNODE];
__device__ float d_bnsum[2][Nn], d_bnsq[2][Nn];

// ---------------- tf32 helpers ----------------
__device__ __forceinline__ void split_tf32(float x, float& hi, float& lo) {
    unsigned h; asm("cvt.rna.tf32.f32 %0, %1;" : "=r"(h) : "f"(x));
    float hf = __uint_as_float(h);
    unsigned l; asm("cvt.rna.tf32.f32 %0, %1;" : "=r"(l) : "f"(x - hf));
    hi = hf; lo = __uint_as_float(l);
}
__device__ __forceinline__ float tf32r(float x) {
    unsigned h; asm("cvt.rna.tf32.f32 %0, %1;" : "=r"(h) : "f"(x));
    return __uint_as_float(h);
}

__device__ __forceinline__ void mma8(float* d,
        float a0, float a1, float a2, float a3, float b0, float b1) {
    asm volatile(
        "mma.sync.aligned.m16n8k8.row.col.f32.tf32.tf32.f32 "
        "{%0,%1,%2,%3},{%4,%5,%6,%7},{%8,%9},{%0,%1,%2,%3};"
        : "+f"(d[0]), "+f"(d[1]), "+f"(d[2]), "+f"(d[3])
        : "r"(__float_as_uint(a0)), "r"(__float_as_uint(a1)),
          "r"(__float_as_uint(a2)), "r"(__float_as_uint(a3)),
          "r"(__float_as_uint(b0)), "r"(__float_as_uint(b1)));
}

__device__ __forceinline__ void mma3(float* d,
        const float* ah, const float* al, float bh0, float bh1, float bl0, float bl1) {
    mma8(d, ah[0], ah[1], ah[2], ah[3], bh0, bh1);
    mma8(d, ah[0], ah[1], ah[2], ah[3], bl0, bl1);
    mma8(d, al[0], al[1], al[2], al[3], bh0, bh1);
}

// ---------------- adaptive adjacency ----------------
__global__ void k_adp(const float* __restrict__ nv1, const float* __restrict__ nv2) {
    __shared__ float nv1s[64];
    __shared__ float vals[Nn];
    __shared__ float red[128];
    int n = blockIdx.x, tid = threadIdx.x;
    if (tid < 64) nv1s[tid] = nv1[n*64 + tid];
    __syncthreads();
    float lmax = -1e30f;
    for (int m = tid; m < Nn; m += 128) {
        const float* p = nv2 + m*64;
        float dot = 0.f;
        #pragma unroll
        for (int k = 0; k < 64; k++) dot += nv1s[k]*p[k];
        float v = fmaxf(dot, 0.f);
        vals[m] = v;
        lmax = fmaxf(lmax, v);
    }
    red[tid] = lmax; __syncthreads();
    for (int s = 64; s > 0; s >>= 1) { if (tid < s) red[tid] = fmaxf(red[tid], red[tid+s]); __syncthreads(); }
    float mx = red[0]; __syncthreads();
    float lsum = 0.f;
    for (int m = tid; m < Nn; m += 128) {
        float e = __expf(vals[m] - mx);
        vals[m] = e; lsum += e;
    }
    red[tid] = lsum; __syncthreads();
    for (int s = 64; s > 0; s >>= 1) { if (tid < s) red[tid] += red[tid+s]; __syncthreads(); }
    float inv = 1.f/red[0];
    for (int m = tid; m < Nn; m += 128) d_adp[n*Nn + m] = vals[m]*inv;
}

// ---------------- all hop projections (full 3xTF32): grid (163, 8, 3) ----------------
__global__ void __launch_bounds__(256) k_matmul_all(const float* __restrict__ mem, const float* __restrict__ sentw,
                             const float* __restrict__ gw, const float* __restrict__ gb) {
    extern __shared__ float sm[];
    float* Xhi = sm;            float* Xlo = sm + 4352;
    float* Whi = sm + 8704;     float* Wlo = sm + 13056;
    int hop = blockIdx.z, y = blockIdx.y;
    const float* Mh  = mem + (size_t)hop*BNE;
    const float* Mh1 = mem + (size_t)(hop+1)*BNE;
    const float* Wh  = gw + (size_t)hop*7*4096;
    const float *X, *W, *bias = nullptr; float* out;
    if (y == 0)      { X = Mh;  W = sentw + (size_t)hop*4096; out = d_keysw + (size_t)hop*BNE; }
    else if (y == 1) { X = Mh1; W = Wh; bias = gb + hop*64;   out = d_base  + (size_t)hop*BNE; }
    else             { X = Mh1; W = Wh + (size_t)(y-1)*4096;  out = d_t6 + ((size_t)hop*6 + (y-2))*BNE; }

    int tid = threadIdx.x;
    int rbase = blockIdx.x*64;
    const int R = NNODE;
    for (int idx = tid; idx < 4096; idx += 256) {
        int k = idx >> 6, n = idx & 63;
        float hi, lo; split_tf32(W[idx], hi, lo);
        Whi[n*68 + k] = hi; Wlo[n*68 + k] = lo;
    }
    for (int idx = tid; idx < 4096; idx += 256) {
        int r = idx >> 6, e = idx & 63;
        int rg = rbase + r;
        float v = (rg < R) ? X[(size_t)rg*64 + e] : 0.f;
        float hi, lo; split_tf32(v, hi, lo);
        Xhi[r*68 + e] = hi; Xlo[r*68 + e] = lo;
    }
    __syncthreads();
    int warp = tid >> 5, lane = tid & 31;
    int wm = warp >> 1, wn = warp & 1;
    int ra = wm*16 + (lane >> 2);
    float acc[4][4] = {};
    #pragma unroll
    for (int k8 = 0; k8 < 8; k8++) {
        int e = k8*8 + (lane & 3);
        float ah[4], al[4];
        ah[0] = Xhi[ra*68 + e];     ah[1] = Xhi[(ra+8)*68 + e];
        ah[2] = Xhi[ra*68 + e + 4]; ah[3] = Xhi[(ra+8)*68 + e + 4];
        al[0] = Xlo[ra*68 + e];     al[1] = Xlo[(ra+8)*68 + e];
        al[2] = Xlo[ra*68 + e + 4]; al[3] = Xlo[(ra+8)*68 + e + 4];
        #pragma unroll
        for (int ns = 0; ns < 4; ns++) {
            int nb = wn*32 + ns*8 + (lane >> 2);
            mma3(acc[ns], ah, al, Whi[nb*68 + e], Whi[nb*68 + e + 4],
                                  Wlo[nb*68 + e], Wlo[nb*68 + e + 4]);
        }
    }
    int r1 = rbase + wm*16 + (lane >> 2);
    #pragma unroll
    for (int ns = 0; ns < 4; ns++) {
        int c = wn*32 + ns*8 + (lane & 3)*2;
        float b0 = bias ? bias[c] : 0.f;
        float b1 = bias ? bias[c+1] : 0.f;
        if (r1 < R) {
            out[(size_t)r1*64 + c]     = acc[ns][0] + b0;
            out[(size_t)r1*64 + c + 1] = acc[ns][1] + b1;
        }
        if (r1 + 8 < R) {
            out[(size_t)(r1+8)*64 + c]     = acc[ns][2] + b0;
            out[(size_t)(r1+8)*64 + c + 1] = acc[ns][3] + b1;
        }
    }
}

// ---------------- einsum (2-MMA: A_tf32 x (B_hi + B_lo)): grid (6, 32, 9) -------------
__global__ void __launch_bounds__(256) k_einsum_all(const float* __restrict__ supports, int phase) {
    extern __shared__ float sm[];
    float* Ahi = sm;          // 64*68
    float* Bhi = sm + 4352;   // 64*68
    float* Blo = sm + 8704;   // 64*68
    int z = blockIdx.z;
    int hop = z/3, s = z%3;
    const float* adj = (s < 2) ? supports + (size_t)s*Nn*Nn : d_adp;
    const float *X, *addend; float* out;
    if (phase == 0) {
        X = d_t6 + ((size_t)hop*6 + 2*s + 1)*BNE;
        addend = d_t6 + ((size_t)hop*6 + 2*s)*BNE;
        out = d_t3b + ((size_t)hop*3 + s)*BNE;
    } else {
        X = d_t3b + ((size_t)hop*3 + s)*BNE;
        addend = nullptr;
        out = d_yp + ((size_t)hop*3 + s)*BNE;
    }
    int tid = threadIdx.x;
    int b = blockIdx.y;
    int ng = blockIdx.x*64;
    int warp = tid >> 5, lane = tid & 31;
    int wm = warp >> 1, wn = warp & 1;
    int ra = wm*16 + (lane >> 2);
    float acc[4][4] = {};
    for (int mc = 0; mc < 384; mc += 64) {
        __syncthreads();
        for (int idx = tid; idx < 4096; idx += 256) {
            int i = idx >> 6, j = idx & 63;
            int nr = ng + i, mm = mc + j;
            float v = (nr < Nn && mm < Nn) ? adj[(size_t)nr*Nn + mm] : 0.f;
            Ahi[i*68 + j] = tf32r(v);
        }
        for (int idx = tid; idx < 4096; idx += 256) {
            int k = idx >> 6, e = idx & 63;
            int mm = mc + k;
            float v = (mm < Nn) ? X[(size_t)b*Nn*64 + mm*64 + e] : 0.f;
            float hi, lo; split_tf32(v, hi, lo);
            Bhi[e*68 + k] = hi; Blo[e*68 + k] = lo;
        }
        __syncthreads();
        #pragma unroll
        for (int k8 = 0; k8 < 8; k8++) {
            int m = k8*8 + (lane & 3);
            float a0 = Ahi[ra*68 + m];
            float a1 = Ahi[(ra+8)*68 + m];
            float a2 = Ahi[ra*68 + m + 4];
            float a3 = Ahi[(ra+8)*68 + m + 4];
            #pragma unroll
            for (int ns = 0; ns < 4; ns++) {
                int nb = wn*32 + ns*8 + (lane >> 2);
                mma8(acc[ns], a0, a1, a2, a3, Bhi[nb*68 + m], Bhi[nb*68 + m + 4]);
                mma8(acc[ns], a0, a1, a2, a3, Blo[nb*68 + m], Blo[nb*68 + m + 4]);
            }
        }
    }
    int r1 = ng + wm*16 + (lane >> 2);
    #pragma unroll
    for (int ns = 0; ns < 4; ns++) {
        int e = wn*32 + ns*8 + (lane & 3)*2;
        #pragma unroll
        for (int half = 0; half < 2; half++) {
            int nr = r1 + half*8;
            if (nr < Nn) {
                size_t g = (size_t)b*Nn*64 + (size_t)nr*64 + e;
                float v0 = acc[ns][half*2], v1 = acc[ns][half*2+1];
                if (addend) { v0 += addend[g]; v1 += addend[g+1]; }
                out[g] = v0; out[g+1] = v1;
            }
        }
    }
}

// ---------------- fragment permutes ----------------
__global__ void k_permK(const float* __restrict__ mem) {
    int hop = blockIdx.y;
    int b = blockIdx.x / 6, c = blockIdx.x % 6;
    const float* K = mem + (size_t)hop*BNE + (size_t)b*Nn*64;
    float2* out = d_Kf2 + (size_t)hop*FRAG_PER_HOP + (size_t)(b*6 + c)*FRAG_PER_BC;
    for (int idx = threadIdx.x; idx < FRAG_PER_BC; idx += 256) {
        int kb8 = idx >> 8, k8 = (idx >> 5) & 7, lane = idx & 31;
        int kk = c*64 + kb8*8 + (lane >> 2);
        int e = k8*8 + (lane & 3);
        float v0 = 0.f, v1 = 0.f;
        if (kk < Nn) { v0 = K[(size_t)kk*64 + e]; v1 = K[(size_t)kk*64 + e + 4]; }
        out[idx] = make_float2(tf32r(v0), tf32r(v1));
    }
}

__global__ void k_permV() {
    int hop = blockIdx.y;
    int b = blockIdx.x / 6, c = blockIdx.x % 6;
    const float* Y0 = d_yp + ((size_t)hop*3 + 0)*BNE + (size_t)b*Nn*64;
    const float* Y1 = d_yp + ((size_t)hop*3 + 1)*BNE + (size_t)b*Nn*64;
    const float* Y2 = d_yp + ((size_t)hop*3 + 2)*BNE + (size_t)b*Nn*64;
    float2* out = d_Vf2 + (size_t)hop*FRAG_PER_HOP + (size_t)(b*6 + c)*FRAG_PER_BC;
    for (int idx = threadIdx.x; idx < FRAG_PER_BC; idx += 256) {
        int eb8 = idx >> 8, k8 = (idx >> 5) & 7, lane = idx & 31;
        int e = eb8*8 + (lane >> 2);
        int kk = c*64 + k8*8 + (lane & 3);
        float v0 = 0.f, v1 = 0.f;
        if (kk < Nn)     { size_t g = (size_t)kk*64 + e;     v0 = Y0[g] + Y1[g] + Y2[g]; }
        if (kk + 4 < Nn) { size_t g = (size_t)(kk+4)*64 + e; v1 = Y0[g] + Y1[g] + Y2[g]; }
        out[idx] = make_float2(tf32r(v0), tf32r(v1));
    }
}

// ---------------- GRU step: 32 rows/block, 325 blocks, 192 threads ----------------
__global__ void k_gru(const float* __restrict__ wih, const float* __restrict__ whh,
                      const float* __restrict__ bih, const float* __restrict__ bhh) {
    extern __shared__ float sm[];
    float* hs  = sm;                 // 32*64
    float* Wt  = sm + 2048;          // 64*193
    float* ghs = Wt + 64*193;        // 32*192
    int tid = threadIdx.x;           // 192
    int g0 = blockIdx.x*32;
    for (int idx = tid; idx < 192*64; idx += 192) {
        int j = idx >> 6, k = idx & 63;
        Wt[k*193 + j] = whh[idx];
    }
    for (int idx = tid; idx < 2048; idx += 192) hs[idx] = d_h[(size_t)g0*64 + idx];
    __syncthreads();
    float acc[32] = {};
    const float4* hs4 = reinterpret_cast<const float4*>(hs);
    #pragma unroll
    for (int kq = 0; kq < 16; kq++) {
        float w0 = Wt[(4*kq+0)*193 + tid];
        float w1 = Wt[(4*kq+1)*193 + tid];
        float w2 = Wt[(4*kq+2)*193 + tid];
        float w3 = Wt[(4*kq+3)*193 + tid];
        #pragma unroll
        for (int i = 0; i < 32; i++) {
            float4 hv = hs4[i*16 + kq];
            acc[i] += hv.x*w0 + hv.y*w1 + hv.z*w2 + hv.w*w3;
        }
    }
    float bj = bhh[tid];
    #pragma unroll
    for (int i = 0; i < 32; i++) ghs[i*192 + tid] = acc[i] + bj;
    __syncthreads();
    for (int idx = tid; idx < 2048; idx += 192) {
        int i = idx >> 6, e = idx & 63;
        int g = g0 + i;
        float pv  = d_prev[g];
        float gir = pv*wih[e]      + bih[e];
        float giz = pv*wih[64+e]   + bih[64+e];
        float gin = pv*wih[128+e]  + bih[128+e];
        float ghr = ghs[i*192 + e];
        float ghz = ghs[i*192 + 64 + e];
        float ghn = ghs[i*192 + 128 + e];
        float r = 1.f/(1.f + __expf(-(gir+ghr)));
        float z = 1.f/(1.f + __expf(-(giz+ghz)));
        float nv = tanhf(gin + r*ghn);
        float hold = hs[idx];
        float hn = (1.f - z)*nv + z*hold;
        d_h[(size_t)g*64 + e] = hn;
        d_u[(size_t)g*64 + e] = hn;
    }
    if (tid < 32) d_acc[g0 + tid] = 0.f;
}

// ---------------- attention per hop: 32 q-rows/block, grid (11, 32) ----------------
// pass 1: 1 MMA (Q_tf32 x K_tf32); pass 3: 1 MMA (P_tf32 x V_tf32).
__global__ void __launch_bounds__(256)
k_attn(const float2* __restrict__ Kf, const float2* __restrict__ Vf,
       const float* __restrict__ base, const float* __restrict__ ksw, int buf) {
    extern __shared__ float sm[];
    float* Qs   = sm;                     // 32 x 68 (tf32-rounded)
    float* Ssm  = sm + 2176;              // 32 x 332
    float* invs = sm + 2176 + 10624;      // 32
    int tid = threadIdx.x;                // 256
    int b = blockIdx.y;
    int q0 = blockIdx.x*32;
    int warp = tid >> 5, lane = tid & 31;
    int wm = warp >> 2, wn = warp & 3;
    const size_t bb = (size_t)b*Nn*64;

    for (int idx = tid; idx < 2048; idx += 256) {
        int r = idx >> 6, e = idx & 63;
        int qg = q0 + r;
        float v = (qg < Nn) ? d_u[bb + (size_t)qg*64 + e] : 0.f;
        Qs[r*68 + e] = tf32r(v);
    }
    #pragma unroll
    for (int r = warp*4; r < warp*4 + 4; r++) {
        int qg = q0 + r;
        if (qg < Nn) {
            const float* up = d_u + bb + (size_t)qg*64;
            const float* kp = ksw + bb + (size_t)qg*64;
            float s = up[lane]*kp[lane] + up[32+lane]*kp[32+lane];
            #pragma unroll
            for (int o = 16; o > 0; o >>= 1) s += __shfl_xor_sync(0xffffffffu, s, o);
            if (lane == 0) d_sent[b*Nn + qg] = s*SCALE_INV;
        }
    }
    __syncthreads();

    int ra = wm*16 + (lane >> 2);
    const float2* Kfb = Kf + (size_t)b*6*FRAG_PER_BC;

    // ---- pass 1: scores = Q K^T / 8 (single tf32 MMA) ----
    for (int c = 0; c < 6; c++) {
        float acc[2][4] = {};
        const float2* Kfc = Kfb + c*FRAG_PER_BC;
        #pragma unroll
        for (int k8 = 0; k8 < 8; k8++) {
            int e = k8*8 + (lane & 3);
            float a0 = Qs[ra*68 + e],     a1 = Qs[(ra+8)*68 + e];
            float a2 = Qs[ra*68 + e + 4], a3 = Qs[(ra+8)*68 + e + 4];
            #pragma unroll
            for (int ns = 0; ns < 2; ns++) {
                float2 f = Kfc[(wn*2 + ns)*256 + k8*32 + lane];
                mma8(acc[ns], a0, a1, a2, a3, f.x, f.y);
            }
        }
        #pragma unroll
        for (int ns = 0; ns < 2; ns++) {
            int key = c*64 + (wn*2 + ns)*8 + (lane & 3)*2;
            if (key < Nn) {
                Ssm[ra*332 + key]     = acc[ns][0]*SCALE_INV;
                Ssm[(ra+8)*332 + key] = acc[ns][2]*SCALE_INV;
            }
            if (key + 1 < Nn) {
                Ssm[ra*332 + key + 1]     = acc[ns][1]*SCALE_INV;
                Ssm[(ra+8)*332 + key + 1] = acc[ns][3]*SCALE_INV;
            }
        }
    }
    __syncthreads();

    // ---- pass 2: softmax rows (unnormalized exp) ----
    #pragma unroll
    for (int r = warp*4; r < warp*4 + 4; r++) {
        float mx = -1e30f;
        for (int m = lane; m < Nn; m += 32) mx = fmaxf(mx, Ssm[r*332 + m]);
        #pragma unroll
        for (int o = 16; o > 0; o >>= 1) mx = fmaxf(mx, __shfl_xor_sync(0xffffffffu, mx, o));
        float sum = 0.f;
        for (int m = lane; m < Nn; m += 32) {
            float ev = __expf(Ssm[r*332 + m] - mx);
            Ssm[r*332 + m] = ev;
            sum += ev;
        }
        #pragma unroll
        for (int o = 16; o > 0; o >>= 1) sum += __shfl_xor_sync(0xffffffffu, sum, o);
        if (lane == 0) invs[r] = 1.f/sum;
    }
    __syncthreads();

    // ---- pass 3: O = P_tf32 @ V_hi (one MMA per fragment) ----
    float oacc[2][4] = {};
    const float2* Vfb = Vf + (size_t)b*6*FRAG_PER_BC;
    for (int c = 0; c < 6; c++) {
        const float2* Vfc = Vfb + c*FRAG_PER_BC;
        #pragma unroll
        for (int k8 = 0; k8 < 8; k8++) {
            int m = c*64 + k8*8 + (lane & 3);
            float p0 = (m < Nn)     ? Ssm[ra*332 + m]         : 0.f;
            float p1 = (m < Nn)     ? Ssm[(ra+8)*332 + m]     : 0.f;
            float p2 = (m + 4 < Nn) ? Ssm[ra*332 + m + 4]     : 0.f;
            float p3 = (m + 4 < Nn) ? Ssm[(ra+8)*332 + m + 4] : 0.f;
            float a0 = tf32r(p0), a1 = tf32r(p1), a2 = tf32r(p2), a3 = tf32r(p3);
            #pragma unroll
            for (int ns = 0; ns < 2; ns++) {
                float2 f = Vfc[(wn*2 + ns)*256 + k8*32 + lane];
                mma8(oacc[ns], a0, a1, a2, a3, f.x, f.y);
            }
        }
    }

    // ---- epilogue: opre = oacc*inv + base; BN partial sums ----
    __syncthreads();
    float* rowsum = Qs;
    float* rowsq  = Qs + 32;
    if (tid < 64) Qs[tid] = 0.f;
    __syncthreads();

    float iv1 = invs[ra], iv2 = invs[ra + 8];
    float s1 = 0.f, q1 = 0.f, s2 = 0.f, q2 = 0.f;
    int qg1 = q0 + ra, qg2 = qg1 + 8;
    #pragma unroll
    for (int ns = 0; ns < 2; ns++) {
        int e = (wn*2 + ns)*8 + (lane & 3)*2;
        if (qg1 < Nn) {
            size_t g = bb + (size_t)qg1*64 + e;
            float v0 = oacc[ns][0]*iv1 + base[g];
            float v1 = oacc[ns][1]*iv1 + base[g+1];
            d_opre[g] = v0; d_opre[g+1] = v1;
            s1 += v0 + v1; q1 += v0*v0 + v1*v1;
        }
        if (qg2 < Nn) {
            size_t g = bb + (size_t)qg2*64 + e;
            float v2 = oacc[ns][2]*iv2 + base[g];
            float v3 = oacc[ns][3]*iv2 + base[g+1];
            d_opre[g] = v2; d_opre[g+1] = v3;
            s2 += v2 + v3; q2 += v2*v2 + v3*v3;
        }
    }
    #pragma unroll
    for (int o = 1; o < 4; o <<= 1) {
        s1 += __shfl_xor_sync(0xffffffffu, s1, o);
        q1 += __shfl_xor_sync(0xffffffffu, q1, o);
        s2 += __shfl_xor_sync(0xffffffffu, s2, o);
        q2 += __shfl_xor_sync(0xffffffffu, q2, o);
    }
    if ((lane & 3) == 0) {
        atomicAdd(&rowsum[ra], s1);     atomicAdd(&rowsq[ra], q1);
        atomicAdd(&rowsum[ra + 8], s2); atomicAdd(&rowsq[ra + 8], q2);
    }
    __syncthreads();
    if (tid < 32) {
        int qg = q0 + tid;
        if (qg < Nn) {
            atomicAdd(&d_bnsum[buf][qg], rowsum[tid]);
            atomicAdd(&d_bnsq[buf][qg],  rowsq[tid]);
        }
    }
}

// ---------------- BN apply + u update + sentinel-weighted output accum ----------------
__global__ void k_apply(const float* __restrict__ gamma, const float* __restrict__ beta,
                        const float* __restrict__ outw, const float* __restrict__ outb,
                        float* __restrict__ dout, int step, int lasthop, int buf) {
    int lane = threadIdx.x & 31;
    int g = blockIdx.x*8 + (threadIdx.x >> 5);
    if (blockIdx.x == 0) {
        for (int i = threadIdx.x; i < Nn; i += 256) {
            d_bnsum[buf^1][i] = 0.f;
            d_bnsq[buf^1][i]  = 0.f;
        }
    }
    if (g >= NNODE) return;
    int b = g / Nn, n = g % Nn;
    float mu = d_bnsum[buf][n]*(1.f/2048.f);
    float var = d_bnsq[buf][n]*(1.f/2048.f) - mu*mu;
    float rs = rsqrtf(var + 1e-5f);
    float gm = gamma[n]*rs, bt = beta[n];
    float v1 = (d_opre[(size_t)g*64 + lane]      - mu)*gm + bt;
    float v2 = (d_opre[(size_t)g*64 + 32 + lane] - mu)*gm + bt;
    d_u[(size_t)g*64 + lane]      += v1;
    d_u[(size_t)g*64 + 32 + lane] += v2;
    float dv = v1*outw[lane] + v2*outw[32 + lane];
    #pragma unroll
    for (int o = 16; o > 0; o >>= 1) dv += __shfl_xor_sync(0xffffffffu, dv, o);
    if (lane == 0) {
        float a = d_acc[g] + d_sent[g]*dv;
        d_acc[g] = a;
        if (lasthop) {
            float val = a + outb[0];
            dout[(size_t)b*St*Nn + (size_t)step*Nn + n] = val;
            d_prev[g] = val;
        }
    }
}

// ---------------- host orchestration ----------------
extern "C" void kernel_launch(void* const* d_in, const int* in_sizes, int n_in,
                              void* d_out, int out_size) {
    const float* hidden   = (const float*)d_in[0];
    const float* supports = (const float*)d_in[1];
    const float* memory   = (const float*)d_in[3];
    const float* nv1      = (const float*)d_in[4];
    const float* nv2      = (const float*)d_in[5];
    const float* wih      = (const float*)d_in[6];
    const float* whh      = (const float*)d_in[7];
    const float* bih      = (const float*)d_in[8];
    const float* bhh      = (const float*)d_in[9];
    const float* sentw    = (const float*)d_in[10];
    const float* gamma    = (const float*)d_in[11];
    const float* beta     = (const float*)d_in[12];
    const float* gw       = (const float*)d_in[13];
    const float* gb       = (const float*)d_in[14];
    const float* outw     = (const float*)d_in[15];
    const float* outb     = (const float*)d_in[16];
    float* dout = (float*)d_out;

    void* pv;
    float *p_keysw, *p_base, *p_h, *p_prev, *p_bnsum, *p_bnsq;
    float2 *p_Kf2, *p_Vf2;
    cudaGetSymbolAddress(&pv, d_keysw); p_keysw = (float*)pv;
    cudaGetSymbolAddress(&pv, d_base);  p_base  = (float*)pv;
    cudaGetSymbolAddress(&pv, d_h);     p_h     = (float*)pv;
    cudaGetSymbolAddress(&pv, d_prev);  p_prev  = (float*)pv;
    cudaGetSymbolAddress(&pv, d_bnsum); p_bnsum = (float*)pv;
    cudaGetSymbolAddress(&pv, d_bnsq);  p_bnsq  = (float*)pv;
    cudaGetSymbolAddress(&pv, d_Kf2);   p_Kf2   = (float2*)pv;
    cudaGetSymbolAddress(&pv, d_Vf2);   p_Vf2   = (float2*)pv;

    const int SMEM_MM   = 17408*4;                       // 69632 (matmul_all, full)
    const int SMEM_EIN  = 13056*4;                       // 52224 (2-MMA einsum)
    const int SMEM_ATTN = 12832*4;                       // 51328 (Q tf32-only)
    const int SMEM_GRU  = (2048 + 64*193 + 32*192)*4;    // 82176
    cudaFuncSetAttribute(k_gru,        cudaFuncAttributeMaxDynamicSharedMemorySize, SMEM_GRU);
    cudaFuncSetAttribute(k_attn,       cudaFuncAttributeMaxDynamicSharedMemorySize, SMEM_ATTN);
    cudaFuncSetAttribute(k_matmul_all, cudaFuncAttributeMaxDynamicSharedMemorySize, SMEM_MM);
    cudaFuncSetAttribute(k_einsum_all, cudaFuncAttributeMaxDynamicSharedMemorySize, SMEM_EIN);

    cudaMemcpyAsync(p_h, hidden, (size_t)BNE*sizeof(float), cudaMemcpyDeviceToDevice, 0);
    cudaMemsetAsync(p_prev, 0, (size_t)NNODE*sizeof(float), 0);
    cudaMemsetAsync(p_bnsum, 0, 2*Nn*sizeof(float), 0);
    cudaMemsetAsync(p_bnsq,  0, 2*Nn*sizeof(float), 0);

    // ---- step-invariant precompute ----
    k_adp<<<Nn, 128>>>(nv1, nv2);
    k_matmul_all<<<dim3(163, 8, 3), 256, SMEM_MM>>>(memory, sentw, gw, gb);
    k_einsum_all<<<dim3(6, Bb, 9), 256, SMEM_EIN>>>(supports, 0);
    k_einsum_all<<<dim3(6, Bb, 9), 256, SMEM_EIN>>>(supports, 1);
    k_permK<<<dim3(192, 3), 256>>>(memory);
    k_permV<<<dim3(192, 3), 256>>>();

    // ---- sequential scan ----
    for (int st = 0; st < St; st++) {
        k_gru<<<325, 192, SMEM_GRU>>>(wih, whh, bih, bhh);
        for (int hop = 0; hop < NHOP; hop++) {
            int idx = st*NHOP + hop;
            int buf = idx & 1;
            k_attn<<<dim3(11, Bb), 256, SMEM_ATTN>>>(p_Kf2 + (size_t)hop*FRAG_PER_HOP,
                                                     p_Vf2 + (size_t)hop*FRAG_PER_HOP,
                                                     p_base + (size_t)hop*BNE,
                                                     p_keysw + (size_t)hop*BNE,
                                                     buf);
            k_apply<<<1300, 256>>>(gamma + hop*Nn, beta + hop*Nn, outw, outb,
                                   dout, st, hop == 2 ? 1 : 0, buf);
        }
    }
}

// round 13
// speedup vs baseline: 1.0575x; 1.0575x over previous
#include <cuda_runtime.h>
#include <math.h>

#define Bb 32
#define Nn 325
#define Ee 64
#define St 12
#define NHOP 3
#define NNODE (Bb*Nn)        // 10400
#define BNE (Bb*Nn*Ee)       // 665600
#define SCALE_INV 0.125f
#define FRAG_PER_BC 2048     // 8 groups * 8 k8 * 32 lanes
#define FRAG_PER_HOP (Bb*6*FRAG_PER_BC)

// ---------------- scratch (device globals; no allocation allowed) ----------------
__device__ float d_adp[Nn*Nn];
__device__ float d_keysw[NHOP*BNE];
__device__ float d_base [NHOP*BNE];
__device__ float d_t6 [NHOP*6*BNE];
__device__ float d_t3b[NHOP*3*BNE];
__device__ float d_yp [NHOP*3*BNE];
__device__ float2 d_Kf2[NHOP*FRAG_PER_HOP];
__device__ float2 d_Vf2[NHOP*FRAG_PER_HOP];
__device__ float d_h[BNE], d_u[BNE], d_opre[BNE];
__device__ float d_prev[NNODE], d_sent[NNODE], d_acc[NNODE];
__device__ float d_bnsum[2][Nn], d_bnsq[2][Nn];

// ---------------- tf32 helpers ----------------
__device__ __forceinline__ void split_tf32(float x, float& hi, float& lo) {
    unsigned h; asm("cvt.rna.tf32.f32 %0, %1;" : "=r"(h) : "f"(x));
    float hf = __uint_as_float(h);
    unsigned l; asm("cvt.rna.tf32.f32 %0, %1;" : "=r"(l) : "f"(x - hf));
    hi = hf; lo = __uint_as_float(l);
}
__device__ __forceinline__ float tf32r(float x) {
    unsigned h; asm("cvt.rna.tf32.f32 %0, %1;" : "=r"(h) : "f"(x));
    return __uint_as_float(h);
}

__device__ __forceinline__ void mma8(float* d,
        float a0, float a1, float a2, float a3, float b0, float b1) {
    asm volatile(
        "mma.sync.aligned.m16n8k8.row.col.f32.tf32.tf32.f32 "
        "{%0,%1,%2,%3},{%4,%5,%6,%7},{%8,%9},{%0,%1,%2,%3};"
        : "+f"(d[0]), "+f"(d[1]), "+f"(d[2]), "+f"(d[3])
        : "r"(__float_as_uint(a0)), "r"(__float_as_uint(a1)),
          "r"(__float_as_uint(a2)), "r"(__float_as_uint(a3)),
          "r"(__float_as_uint(b0)), "r"(__float_as_uint(b1)));
}

__device__ __forceinline__ void mma3(float* d,
        const float* ah, const float* al, float bh0, float bh1, float bl0, float bl1) {
    mma8(d, ah[0], ah[1], ah[2], ah[3], bh0, bh1);
    mma8(d, ah[0], ah[1], ah[2], ah[3], bl0, bl1);
    mma8(d, al[0], al[1], al[2], al[3], bh0, bh1);
}

// ---------------- adaptive adjacency ----------------
__global__ void k_adp(const float* __restrict__ nv1, const float* __restrict__ nv2) {
    __shared__ float nv1s[64];
    __shared__ float vals[Nn];
    __shared__ float red[128];
    int n = blockIdx.x, tid = threadIdx.x;
    if (tid < 64) nv1s[tid] = nv1[n*64 + tid];
    __syncthreads();
    float lmax = -1e30f;
    for (int m = tid; m < Nn; m += 128) {
        const float* p = nv2 + m*64;
        float dot = 0.f;
        #pragma unroll
        for (int k = 0; k < 64; k++) dot += nv1s[k]*p[k];
        float v = fmaxf(dot, 0.f);
        vals[m] = v;
        lmax = fmaxf(lmax, v);
    }
    red[tid] = lmax; __syncthreads();
    for (int s = 64; s > 0; s >>= 1) { if (tid < s) red[tid] = fmaxf(red[tid], red[tid+s]); __syncthreads(); }
    float mx = red[0]; __syncthreads();
    float lsum = 0.f;
    for (int m = tid; m < Nn; m += 128) {
        float e = __expf(vals[m] - mx);
        vals[m] = e; lsum += e;
    }
    red[tid] = lsum; __syncthreads();
    for (int s = 64; s > 0; s >>= 1) { if (tid < s) red[tid] += red[tid+s]; __syncthreads(); }
    float inv = 1.f/red[0];
    for (int m = tid; m < Nn; m += 128) d_adp[n*Nn + m] = vals[m]*inv;
}

// ---------------- all hop projections (full 3xTF32): grid (163, 8, 3) ----------------
__global__ void __launch_bounds__(256) k_matmul_all(const float* __restrict__ mem, const float* __restrict__ sentw,
                             const float* __restrict__ gw, const float* __restrict__ gb) {
    extern __shared__ float sm[];
    float* Xhi = sm;            float* Xlo = sm + 4352;
    float* Whi = sm + 8704;     float* Wlo = sm + 13056;
    int hop = blockIdx.z, y = blockIdx.y;
    const float* Mh  = mem + (size_t)hop*BNE;
    const float* Mh1 = mem + (size_t)(hop+1)*BNE;
    const float* Wh  = gw + (size_t)hop*7*4096;
    const float *X, *W, *bias = nullptr; float* out;
    if (y == 0)      { X = Mh;  W = sentw + (size_t)hop*4096; out = d_keysw + (size_t)hop*BNE; }
    else if (y == 1) { X = Mh1; W = Wh; bias = gb + hop*64;   out = d_base  + (size_t)hop*BNE; }
    else             { X = Mh1; W = Wh + (size_t)(y-1)*4096;  out = d_t6 + ((size_t)hop*6 + (y-2))*BNE; }

    int tid = threadIdx.x;
    int rbase = blockIdx.x*64;
    const int R = NNODE;
    for (int idx = tid; idx < 4096; idx += 256) {
        int k = idx >> 6, n = idx & 63;
        float hi, lo; split_tf32(W[idx], hi, lo);
        Whi[n*68 + k] = hi; Wlo[n*68 + k] = lo;
    }
    for (int idx = tid; idx < 4096; idx += 256) {
        int r = idx >> 6, e = idx & 63;
        int rg = rbase + r;
        float v = (rg < R) ? X[(size_t)rg*64 + e] : 0.f;
        float hi, lo; split_tf32(v, hi, lo);
        Xhi[r*68 + e] = hi; Xlo[r*68 + e] = lo;
    }
    __syncthreads();
    int warp = tid >> 5, lane = tid & 31;
    int wm = warp >> 1, wn = warp & 1;
    int ra = wm*16 + (lane >> 2);
    float acc[4][4] = {};
    #pragma unroll
    for (int k8 = 0; k8 < 8; k8++) {
        int e = k8*8 + (lane & 3);
        float ah[4], al[4];
        ah[0] = Xhi[ra*68 + e];     ah[1] = Xhi[(ra+8)*68 + e];
        ah[2] = Xhi[ra*68 + e + 4]; ah[3] = Xhi[(ra+8)*68 + e + 4];
        al[0] = Xlo[ra*68 + e];     al[1] = Xlo[(ra+8)*68 + e];
        al[2] = Xlo[ra*68 + e + 4]; al[3] = Xlo[(ra+8)*68 + e + 4];
        #pragma unroll
        for (int ns = 0; ns < 4; ns++) {
            int nb = wn*32 + ns*8 + (lane >> 2);
            mma3(acc[ns], ah, al, Whi[nb*68 + e], Whi[nb*68 + e + 4],
                                  Wlo[nb*68 + e], Wlo[nb*68 + e + 4]);
        }
    }
    int r1 = rbase + wm*16 + (lane >> 2);
    #pragma unroll
    for (int ns = 0; ns < 4; ns++) {
        int c = wn*32 + ns*8 + (lane & 3)*2;
        float b0 = bias ? bias[c] : 0.f;
        float b1 = bias ? bias[c+1] : 0.f;
        if (r1 < R) {
            out[(size_t)r1*64 + c]     = acc[ns][0] + b0;
            out[(size_t)r1*64 + c + 1] = acc[ns][1] + b1;
        }
        if (r1 + 8 < R) {
            out[(size_t)(r1+8)*64 + c]     = acc[ns][2] + b0;
            out[(size_t)(r1+8)*64 + c + 1] = acc[ns][3] + b1;
        }
    }
}

// ---------------- einsum (2-MMA, A staged once per 2 b's): grid (6, 16, 9) ------------
__global__ void __launch_bounds__(256) k_einsum_all(const float* __restrict__ supports, int phase) {
    extern __shared__ float sm[];
    float* Ahi = sm;          // 64*68
    float* Bhi = sm + 4352;   // 64*68
    float* Blo = sm + 8704;   // 64*68
    int z = blockIdx.z;
    int hop = z/3, s = z%3;
    const float* adj = (s < 2) ? supports + (size_t)s*Nn*Nn : d_adp;
    const float *Xb, *addb; float* outb_;
    if (phase == 0) {
        Xb   = d_t6 + ((size_t)hop*6 + 2*s + 1)*BNE;
        addb = d_t6 + ((size_t)hop*6 + 2*s)*BNE;
        outb_ = d_t3b + ((size_t)hop*3 + s)*BNE;
    } else {
        Xb   = d_t3b + ((size_t)hop*3 + s)*BNE;
        addb = nullptr;
        outb_ = d_yp + ((size_t)hop*3 + s)*BNE;
    }
    int tid = threadIdx.x;
    int b0 = blockIdx.y*2;
    int ng = blockIdx.x*64;
    int warp = tid >> 5, lane = tid & 31;
    int wm = warp >> 1, wn = warp & 1;
    int ra = wm*16 + (lane >> 2);
    float acc[2][4][4] = {};
    for (int mc = 0; mc < 384; mc += 64) {
        __syncthreads();    // prior mma done reading A
        for (int idx = tid; idx < 4096; idx += 256) {
            int i = idx >> 6, j = idx & 63;
            int nr = ng + i, mm = mc + j;
            float v = (nr < Nn && mm < Nn) ? adj[(size_t)nr*Nn + mm] : 0.f;
            Ahi[i*68 + j] = tf32r(v);
        }
        #pragma unroll
        for (int q = 0; q < 2; q++) {
            __syncthreads();    // A visible (q=0) / prior mma done reading B
            const float* X = Xb + (size_t)(b0 + q)*Nn*64;
            for (int idx = tid; idx < 4096; idx += 256) {
                int k = idx >> 6, e = idx & 63;
                int mm = mc + k;
                float v = (mm < Nn) ? X[(size_t)mm*64 + e] : 0.f;
                float hi, lo; split_tf32(v, hi, lo);
                Bhi[e*68 + k] = hi; Blo[e*68 + k] = lo;
            }
            __syncthreads();    // B visible
            #pragma unroll
            for (int k8 = 0; k8 < 8; k8++) {
                int m = k8*8 + (lane & 3);
                float a0 = Ahi[ra*68 + m];
                float a1 = Ahi[(ra+8)*68 + m];
                float a2 = Ahi[ra*68 + m + 4];
                float a3 = Ahi[(ra+8)*68 + m + 4];
                #pragma unroll
                for (int ns = 0; ns < 4; ns++) {
                    int nb = wn*32 + ns*8 + (lane >> 2);
                    mma8(acc[q][ns], a0, a1, a2, a3, Bhi[nb*68 + m], Bhi[nb*68 + m + 4]);
                    mma8(acc[q][ns], a0, a1, a2, a3, Blo[nb*68 + m], Blo[nb*68 + m + 4]);
                }
            }
        }
    }
    int r1 = ng + wm*16 + (lane >> 2);
    #pragma unroll
    for (int q = 0; q < 2; q++) {
        int b = b0 + q;
        #pragma unroll
        for (int ns = 0; ns < 4; ns++) {
            int e = wn*32 + ns*8 + (lane & 3)*2;
            #pragma unroll
            for (int half = 0; half < 2; half++) {
                int nr = r1 + half*8;
                if (nr < Nn) {
                    size_t g = (size_t)b*Nn*64 + (size_t)nr*64 + e;
                    float v0 = acc[q][ns][half*2], v1 = acc[q][ns][half*2+1];
                    if (addb) { v0 += addb[g]; v1 += addb[g+1]; }
                    outb_[g] = v0; outb_[g+1] = v1;
                }
            }
        }
    }
}

// ---------------- fragment permutes ----------------
__global__ void k_permK(const float* __restrict__ mem) {
    int hop = blockIdx.y;
    int b = blockIdx.x / 6, c = blockIdx.x % 6;
    const float* K = mem + (size_t)hop*BNE + (size_t)b*Nn*64;
    float2* out = d_Kf2 + (size_t)hop*FRAG_PER_HOP + (size_t)(b*6 + c)*FRAG_PER_BC;
    for (int idx = threadIdx.x; idx < FRAG_PER_BC; idx += 256) {
        int kb8 = idx >> 8, k8 = (idx >> 5) & 7, lane = idx & 31;
        int kk = c*64 + kb8*8 + (lane >> 2);
        int e = k8*8 + (lane & 3);
        float v0 = 0.f, v1 = 0.f;
        if (kk < Nn) { v0 = K[(size_t)kk*64 + e]; v1 = K[(size_t)kk*64 + e + 4]; }
        out[idx] = make_float2(tf32r(v0), tf32r(v1));
    }
}

__global__ void k_permV() {
    int hop = blockIdx.y;
    int b = blockIdx.x / 6, c = blockIdx.x % 6;
    const float* Y0 = d_yp + ((size_t)hop*3 + 0)*BNE + (size_t)b*Nn*64;
    const float* Y1 = d_yp + ((size_t)hop*3 + 1)*BNE + (size_t)b*Nn*64;
    const float* Y2 = d_yp + ((size_t)hop*3 + 2)*BNE + (size_t)b*Nn*64;
    float2* out = d_Vf2 + (size_t)hop*FRAG_PER_HOP + (size_t)(b*6 + c)*FRAG_PER_BC;
    for (int idx = threadIdx.x; idx < FRAG_PER_BC; idx += 256) {
        int eb8 = idx >> 8, k8 = (idx >> 5) & 7, lane = idx & 31;
        int e = eb8*8 + (lane >> 2);
        int kk = c*64 + k8*8 + (lane & 3);
        float v0 = 0.f, v1 = 0.f;
        if (kk < Nn)     { size_t g = (size_t)kk*64 + e;     v0 = Y0[g] + Y1[g] + Y2[g]; }
        if (kk + 4 < Nn) { size_t g = (size_t)(kk+4)*64 + e; v1 = Y0[g] + Y1[g] + Y2[g]; }
        out[idx] = make_float2(tf32r(v0), tf32r(v1));
    }
}

// ---------------- GRU step: 32 rows/block, 325 blocks, 192 threads ----------------
__global__ void k_gru(const float* __restrict__ wih, const float* __restrict__ whh,
                      const float* __restrict__ bih, const float* __restrict__ bhh) {
    extern __shared__ float sm[];
    float* hs  = sm;                 // 32*64
    float* Wt  = sm + 2048;          // 64*193
    float* ghs = Wt + 64*193;        // 32*192
    int tid = threadIdx.x;           // 192
    int g0 = blockIdx.x*32;
    for (int idx = tid; idx < 192*64; idx += 192) {
        int j = idx >> 6, k = idx & 63;
        Wt[k*193 + j] = whh[idx];
    }
    for (int idx = tid; idx < 2048; idx += 192) hs[idx] = d_h[(size_t)g0*64 + idx];
    __syncthreads();
    float acc[32] = {};
    const float4* hs4 = reinterpret_cast<const float4*>(hs);
    #pragma unroll
    for (int kq = 0; kq < 16; kq++) {
        float w0 = Wt[(4*kq+0)*193 + tid];
        float w1 = Wt[(4*kq+1)*193 + tid];
        float w2 = Wt[(4*kq+2)*193 + tid];
        float w3 = Wt[(4*kq+3)*193 + tid];
        #pragma unroll
        for (int i = 0; i < 32; i++) {
            float4 hv = hs4[i*16 + kq];
            acc[i] += hv.x*w0 + hv.y*w1 + hv.z*w2 + hv.w*w3;
        }
    }
    float bj = bhh[tid];
    #pragma unroll
    for (int i = 0; i < 32; i++) ghs[i*192 + tid] = acc[i] + bj;
    __syncthreads();
    for (int idx = tid; idx < 2048; idx += 192) {
        int i = idx >> 6, e = idx & 63;
        int g = g0 + i;
        float pv  = d_prev[g];
        float gir = pv*wih[e]      + bih[e];
        float giz = pv*wih[64+e]   + bih[64+e];
        float gin = pv*wih[128+e]  + bih[128+e];
        float ghr = ghs[i*192 + e];
        float ghz = ghs[i*192 + 64 + e];
        float ghn = ghs[i*192 + 128 + e];
        float r = 1.f/(1.f + __expf(-(gir+ghr)));
        float z = 1.f/(1.f + __expf(-(giz+ghz)));
        float nv = tanhf(gin + r*ghn);
        float hold = hs[idx];
        float hn = (1.f - z)*nv + z*hold;
        d_h[(size_t)g*64 + e] = hn;
        d_u[(size_t)g*64 + e] = hn;
    }
    if (tid < 32) d_acc[g0 + tid] = 0.f;
}

// ---------------- attention per hop: 32 q-rows/block, grid (11, 32) (R11 exact) --------
// pass 1: 2 MMAs ((Q_hi + Q_lo) x K_tf32); pass 3: 1 MMA (P_tf32 x V_tf32).
__global__ void __launch_bounds__(256)
k_attn(const float2* __restrict__ Kf, const float2* __restrict__ Vf,
       const float* __restrict__ base, const float* __restrict__ ksw, int buf) {
    extern __shared__ float sm[];
    float* Qhi  = sm;
    float* Qlo  = sm + 2176;
    float* Ssm  = sm + 4352;              // 32 x 332
    float* invs = sm + 4352 + 10624;      // 32
    int tid = threadIdx.x;                // 256
    int b = blockIdx.y;
    int q0 = blockIdx.x*32;
    int warp = tid >> 5, lane = tid & 31;
    int wm = warp >> 2, wn = warp & 3;
    const size_t bb = (size_t)b*Nn*64;

    for (int idx = tid; idx < 2048; idx += 256) {
        int r = idx >> 6, e = idx & 63;
        int qg = q0 + r;
        float v = (qg < Nn) ? d_u[bb + (size_t)qg*64 + e] : 0.f;
        float hi, lo; split_tf32(v, hi, lo);
        Qhi[r*68 + e] = hi; Qlo[r*68 + e] = lo;
    }
    #pragma unroll
    for (int r = warp*4; r < warp*4 + 4; r++) {
        int qg = q0 + r;
        if (qg < Nn) {
            const float* up = d_u + bb + (size_t)qg*64;
            const float* kp = ksw + bb + (size_t)qg*64;
            float s = up[lane]*kp[lane] + up[32+lane]*kp[32+lane];
            #pragma unroll
            for (int o = 16; o > 0; o >>= 1) s += __shfl_xor_sync(0xffffffffu, s, o);
            if (lane == 0) d_sent[b*Nn + qg] = s*SCALE_INV;
        }
    }
    __syncthreads();

    int ra = wm*16 + (lane >> 2);
    const float2* Kfb = Kf + (size_t)b*6*FRAG_PER_BC;

    // ---- pass 1: scores = Q K^T / 8 (2 MMAs, K single tf32) ----
    for (int c = 0; c < 6; c++) {
        float acc[2][4] = {};
        const float2* Kfc = Kfb + c*FRAG_PER_BC;
        #pragma unroll
        for (int k8 = 0; k8 < 8; k8++) {
            int e = k8*8 + (lane & 3);
            float ah0 = Qhi[ra*68 + e],     ah1 = Qhi[(ra+8)*68 + e];
            float ah2 = Qhi[ra*68 + e + 4], ah3 = Qhi[(ra+8)*68 + e + 4];
            float al0 = Qlo[ra*68 + e],     al1 = Qlo[(ra+8)*68 + e];
            float al2 = Qlo[ra*68 + e + 4], al3 = Qlo[(ra+8)*68 + e + 4];
            #pragma unroll
            for (int ns = 0; ns < 2; ns++) {
                float2 f = Kfc[(wn*2 + ns)*256 + k8*32 + lane];
                mma8(acc[ns], ah0, ah1, ah2, ah3, f.x, f.y);
                mma8(acc[ns], al0, al1, al2, al3, f.x, f.y);
            }
        }
        #pragma unroll
        for (int ns = 0; ns < 2; ns++) {
            int key = c*64 + (wn*2 + ns)*8 + (lane & 3)*2;
            if (key < Nn) {
                Ssm[ra*332 + key]     = acc[ns][0]*SCALE_INV;
                Ssm[(ra+8)*332 + key] = acc[ns][2]*SCALE_INV;
            }
            if (key + 1 < Nn) {
                Ssm[ra*332 + key + 1]     = acc[ns][1]*SCALE_INV;
                Ssm[(ra+8)*332 + key + 1] = acc[ns][3]*SCALE_INV;
            }
        }
    }
    __syncthreads();

    // ---- pass 2: softmax rows (unnormalized exp) ----
    #pragma unroll
    for (int r = warp*4; r < warp*4 + 4; r++) {
        float mx = -1e30f;
        for (int m = lane; m < Nn; m += 32) mx = fmaxf(mx, Ssm[r*332 + m]);
        #pragma unroll
        for (int o = 16; o > 0; o >>= 1) mx = fmaxf(mx, __shfl_xor_sync(0xffffffffu, mx, o));
        float sum = 0.f;
        for (int m = lane; m < Nn; m += 32) {
            float ev = __expf(Ssm[r*332 + m] - mx);
            Ssm[r*332 + m] = ev;
            sum += ev;
        }
        #pragma unroll
        for (int o = 16; o > 0; o >>= 1) sum += __shfl_xor_sync(0xffffffffu, sum, o);
        if (lane == 0) invs[r] = 1.f/sum;
    }
    __syncthreads();

    // ---- pass 3: O = P_tf32 @ V_hi (one MMA per fragment) ----
    float oacc[2][4] = {};
    const float2* Vfb = Vf + (size_t)b*6*FRAG_PER_BC;
    for (int c = 0; c < 6; c++) {
        const float2* Vfc = Vfb + c*FRAG_PER_BC;
        #pragma unroll
        for (int k8 = 0; k8 < 8; k8++) {
            int m = c*64 + k8*8 + (lane & 3);
            float p0 = (m < Nn)     ? Ssm[ra*332 + m]         : 0.f;
            float p1 = (m < Nn)     ? Ssm[(ra+8)*332 + m]     : 0.f;
            float p2 = (m + 4 < Nn) ? Ssm[ra*332 + m + 4]     : 0.f;
            float p3 = (m + 4 < Nn) ? Ssm[(ra+8)*332 + m + 4] : 0.f;
            float a0 = tf32r(p0), a1 = tf32r(p1), a2 = tf32r(p2), a3 = tf32r(p3);
            #pragma unroll
            for (int ns = 0; ns < 2; ns++) {
                float2 f = Vfc[(wn*2 + ns)*256 + k8*32 + lane];
                mma8(oacc[ns], a0, a1, a2, a3, f.x, f.y);
            }
        }
    }

    // ---- epilogue: opre = oacc*inv + base; BN partial sums ----
    __syncthreads();
    float* rowsum = Qhi;
    float* rowsq  = Qhi + 32;
    if (tid < 64) Qhi[tid] = 0.f;
    __syncthreads();

    float iv1 = invs[ra], iv2 = invs[ra + 8];
    float s1 = 0.f, q1 = 0.f, s2 = 0.f, q2 = 0.f;
    int qg1 = q0 + ra, qg2 = qg1 + 8;
    #pragma unroll
    for (int ns = 0; ns < 2; ns++) {
        int e = (wn*2 + ns)*8 + (lane & 3)*2;
        if (qg1 < Nn) {
            size_t g = bb + (size_t)qg1*64 + e;
            float v0 = oacc[ns][0]*iv1 + base[g];
            float v1 = oacc[ns][1]*iv1 + base[g+1];
            d_opre[g] = v0; d_opre[g+1] = v1;
            s1 += v0 + v1; q1 += v0*v0 + v1*v1;
        }
        if (qg2 < Nn) {
            size_t g = bb + (size_t)qg2*64 + e;
            float v2 = oacc[ns][2]*iv2 + base[g];
            float v3 = oacc[ns][3]*iv2 + base[g+1];
            d_opre[g] = v2; d_opre[g+1] = v3;
            s2 += v2 + v3; q2 += v2*v2 + v3*v3;
        }
    }
    #pragma unroll
    for (int o = 1; o < 4; o <<= 1) {
        s1 += __shfl_xor_sync(0xffffffffu, s1, o);
        q1 += __shfl_xor_sync(0xffffffffu, q1, o);
        s2 += __shfl_xor_sync(0xffffffffu, s2, o);
        q2 += __shfl_xor_sync(0xffffffffu, q2, o);
    }
    if ((lane & 3) == 0) {
        atomicAdd(&rowsum[ra], s1);     atomicAdd(&rowsq[ra], q1);
        atomicAdd(&rowsum[ra + 8], s2); atomicAdd(&rowsq[ra + 8], q2);
    }
    __syncthreads();
    if (tid < 32) {
        int qg = q0 + tid;
        if (qg < Nn) {
            atomicAdd(&d_bnsum[buf][qg], rowsum[tid]);
            atomicAdd(&d_bnsq[buf][qg],  rowsq[tid]);
        }
    }
}

// ---------------- BN apply + u update + sentinel-weighted output accum ----------------
__global__ void k_apply(const float* __restrict__ gamma, const float* __restrict__ beta,
                        const float* __restrict__ outw, const float* __restrict__ outb,
                        float* __restrict__ dout, int step, int lasthop, int buf) {
    int lane = threadIdx.x & 31;
    int g = blockIdx.x*8 + (threadIdx.x >> 5);
    if (blockIdx.x == 0) {
        for (int i = threadIdx.x; i < Nn; i += 256) {
            d_bnsum[buf^1][i] = 0.f;
            d_bnsq[buf^1][i]  = 0.f;
        }
    }
    if (g >= NNODE) return;
    int b = g / Nn, n = g % Nn;
    float mu = d_bnsum[buf][n]*(1.f/2048.f);
    float var = d_bnsq[buf][n]*(1.f/2048.f) - mu*mu;
    float rs = rsqrtf(var + 1e-5f);
    float gm = gamma[n]*rs, bt = beta[n];
    float v1 = (d_opre[(size_t)g*64 + lane]      - mu)*gm + bt;
    float v2 = (d_opre[(size_t)g*64 + 32 + lane] - mu)*gm + bt;
    d_u[(size_t)g*64 + lane]      += v1;
    d_u[(size_t)g*64 + 32 + lane] += v2;
    float dv = v1*outw[lane] + v2*outw[32 + lane];
    #pragma unroll
    for (int o = 16; o > 0; o >>= 1) dv += __shfl_xor_sync(0xffffffffu, dv, o);
    if (lane == 0) {
        float a = d_acc[g] + d_sent[g]*dv;
        d_acc[g] = a;
        if (lasthop) {
            float val = a + outb[0];
            dout[(size_t)b*St*Nn + (size_t)step*Nn + n] = val;
            d_prev[g] = val;
        }
    }
}

// ---------------- host orchestration ----------------
extern "C" void kernel_launch(void* const* d_in, const int* in_sizes, int n_in,
                              void* d_out, int out_size) {
    const float* hidden   = (const float*)d_in[0];
    const float* supports = (const float*)d_in[1];
    const float* memory   = (const float*)d_in[3];
    const float* nv1      = (const float*)d_in[4];
    const float* nv2      = (const float*)d_in[5];
    const float* wih      = (const float*)d_in[6];
    const float* whh      = (const float*)d_in[7];
    const float* bih      = (const float*)d_in[8];
    const float* bhh      = (const float*)d_in[9];
    const float* sentw    = (const float*)d_in[10];
    const float* gamma    = (const float*)d_in[11];
    const float* beta     = (const float*)d_in[12];
    const float* gw       = (const float*)d_in[13];
    const float* gb       = (const float*)d_in[14];
    const float* outw     = (const float*)d_in[15];
    const float* outb     = (const float*)d_in[16];
    float* dout = (float*)d_out;

    void* pv;
    float *p_keysw, *p_base, *p_h, *p_prev, *p_bnsum, *p_bnsq;
    float2 *p_Kf2, *p_Vf2;
    cudaGetSymbolAddress(&pv, d_keysw); p_keysw = (float*)pv;
    cudaGetSymbolAddress(&pv, d_base);  p_base  = (float*)pv;
    cudaGetSymbolAddress(&pv, d_h);     p_h     = (float*)pv;
    cudaGetSymbolAddress(&pv, d_prev);  p_prev  = (float*)pv;
    cudaGetSymbolAddress(&pv, d_bnsum); p_bnsum = (float*)pv;
    cudaGetSymbolAddress(&pv, d_bnsq);  p_bnsq  = (float*)pv;
    cudaGetSymbolAddress(&pv, d_Kf2);   p_Kf2   = (float2*)pv;
    cudaGetSymbolAddress(&pv, d_Vf2);   p_Vf2   = (float2*)pv;

    const int SMEM_MM   = 17408*4;                       // 69632 (matmul_all, full)
    const int SMEM_EIN  = 13056*4;                       // 52224 (2-MMA einsum)
    const int SMEM_ATTN = 15008*4;                       // 60032
    const int SMEM_GRU  = (2048 + 64*193 + 32*192)*4;    // 82176
    cudaFuncSetAttribute(k_gru,        cudaFuncAttributeMaxDynamicSharedMemorySize, SMEM_GRU);
    cudaFuncSetAttribute(k_attn,       cudaFuncAttributeMaxDynamicSharedMemorySize, SMEM_ATTN);
    cudaFuncSetAttribute(k_matmul_all, cudaFuncAttributeMaxDynamicSharedMemorySize, SMEM_MM);
    cudaFuncSetAttribute(k_einsum_all, cudaFuncAttributeMaxDynamicSharedMemorySize, SMEM_EIN);

    cudaMemcpyAsync(p_h, hidden, (size_t)BNE*sizeof(float), cudaMemcpyDeviceToDevice, 0);
    cudaMemsetAsync(p_prev, 0, (size_t)NNODE*sizeof(float), 0);
    cudaMemsetAsync(p_bnsum, 0, 2*Nn*sizeof(float), 0);
    cudaMemsetAsync(p_bnsq,  0, 2*Nn*sizeof(float), 0);

    // ---- step-invariant precompute ----
    k_adp<<<Nn, 128>>>(nv1, nv2);
    k_matmul_all<<<dim3(163, 8, 3), 256, SMEM_MM>>>(memory, sentw, gw, gb);
    k_einsum_all<<<dim3(6, 16, 9), 256, SMEM_EIN>>>(supports, 0);
    k_einsum_all<<<dim3(6, 16, 9), 256, SMEM_EIN>>>(supports, 1);
    k_permK<<<dim3(192, 3), 256>>>(memory);
    k_permV<<<dim3(192, 3), 256>>>();

    // ---- sequential scan (R11 exact structure) ----
    for (int st = 0; st < St; st++) {
        k_gru<<<325, 192, SMEM_GRU>>>(wih, whh, bih, bhh);
        for (int hop = 0; hop < NHOP; hop++) {
            int idx = st*NHOP + hop;
            int buf = idx & 1;
            k_attn<<<dim3(11, Bb), 256, SMEM_ATTN>>>(p_Kf2 + (size_t)hop*FRAG_PER_HOP,
                                                     p_Vf2 + (size_t)hop*FRAG_PER_HOP,
                                                     p_base + (size_t)hop*BNE,
                                                     p_keysw + (size_t)hop*BNE,
                                                     buf);
            k_apply<<<1300, 256>>>(gamma + hop*Nn, beta + hop*Nn, outw, outb,
                                   dout, st, hop == 2 ? 1 : 0, buf);
        }
    }
}

// round 14
// speedup vs baseline: 1.0736x; 1.0152x over previous
#include <cuda_runtime.h>
#include <math.h>

#define Bb 32
#define Nn 325
#define Ee 64
#define St 12
#define NHOP 3
#define NNODE (Bb*Nn)        // 10400
#define BNE (Bb*Nn*Ee)       // 665600
#define SCALE_INV 0.125f
#define FRAG4_PER_BC 1024    // 4 pairs * 8 k8 * 32 lanes (float4 each)
#define FRAG4_PER_HOP (Bb*6*FRAG4_PER_BC)

// ---------------- scratch (device globals; no allocation allowed) ----------------
__device__ float d_adp[Nn*Nn];
__device__ float d_keysw[NHOP*BNE];
__device__ float d_base [NHOP*BNE];
__device__ float d_t6 [NHOP*6*BNE];
__device__ float d_t3b[NHOP*3*BNE];
__device__ float d_yp [NHOP*3*BNE];
__device__ float4 d_Kf4[NHOP*FRAG4_PER_HOP];
__device__ float4 d_Vf4[NHOP*FRAG4_PER_HOP];
__device__ float d_h[BNE], d_u[BNE], d_opre[BNE];
__device__ float d_prev[NNODE], d_sent[NNODE], d_acc[NNODE];
__device__ float d_bnsum[2][Nn], d_bnsq[2][Nn];

// ---------------- tf32 helpers ----------------
__device__ __forceinline__ void split_tf32(float x, float& hi, float& lo) {
    unsigned h; asm("cvt.rna.tf32.f32 %0, %1;" : "=r"(h) : "f"(x));
    float hf = __uint_as_float(h);
    unsigned l; asm("cvt.rna.tf32.f32 %0, %1;" : "=r"(l) : "f"(x - hf));
    hi = hf; lo = __uint_as_float(l);
}
__device__ __forceinline__ float tf32r(float x) {
    unsigned h; asm("cvt.rna.tf32.f32 %0, %1;" : "=r"(h) : "f"(x));
    return __uint_as_float(h);
}

__device__ __forceinline__ void mma8(float* d,
        float a0, float a1, float a2, float a3, float b0, float b1) {
    asm volatile(
        "mma.sync.aligned.m16n8k8.row.col.f32.tf32.tf32.f32 "
        "{%0,%1,%2,%3},{%4,%5,%6,%7},{%8,%9},{%0,%1,%2,%3};"
        : "+f"(d[0]), "+f"(d[1]), "+f"(d[2]), "+f"(d[3])
        : "r"(__float_as_uint(a0)), "r"(__float_as_uint(a1)),
          "r"(__float_as_uint(a2)), "r"(__float_as_uint(a3)),
          "r"(__float_as_uint(b0)), "r"(__float_as_uint(b1)));
}

__device__ __forceinline__ void mma3(float* d,
        const float* ah, const float* al, float bh0, float bh1, float bl0, float bl1) {
    mma8(d, ah[0], ah[1], ah[2], ah[3], bh0, bh1);
    mma8(d, ah[0], ah[1], ah[2], ah[3], bl0, bl1);
    mma8(d, al[0], al[1], al[2], al[3], bh0, bh1);
}

// ---------------- adaptive adjacency ----------------
__global__ void k_adp(const float* __restrict__ nv1, const float* __restrict__ nv2) {
    __shared__ float nv1s[64];
    __shared__ float vals[Nn];
    __shared__ float red[128];
    int n = blockIdx.x, tid = threadIdx.x;
    if (tid < 64) nv1s[tid] = nv1[n*64 + tid];
    __syncthreads();
    float lmax = -1e30f;
    for (int m = tid; m < Nn; m += 128) {
        const float* p = nv2 + m*64;
        float dot = 0.f;
        #pragma unroll
        for (int k = 0; k < 64; k++) dot += nv1s[k]*p[k];
        float v = fmaxf(dot, 0.f);
        vals[m] = v;
        lmax = fmaxf(lmax, v);
    }
    red[tid] = lmax; __syncthreads();
    for (int s = 64; s > 0; s >>= 1) { if (tid < s) red[tid] = fmaxf(red[tid], red[tid+s]); __syncthreads(); }
    float mx = red[0]; __syncthreads();
    float lsum = 0.f;
    for (int m = tid; m < Nn; m += 128) {
        float e = __expf(vals[m] - mx);
        vals[m] = e; lsum += e;
    }
    red[tid] = lsum; __syncthreads();
    for (int s = 64; s > 0; s >>= 1) { if (tid < s) red[tid] += red[tid+s]; __syncthreads(); }
    float inv = 1.f/red[0];
    for (int m = tid; m < Nn; m += 128) d_adp[n*Nn + m] = vals[m]*inv;
}

// ---------------- all hop projections (full 3xTF32): grid (163, 8, 3) ----------------
__global__ void __launch_bounds__(256) k_matmul_all(const float* __restrict__ mem, const float* __restrict__ sentw,
                             const float* __restrict__ gw, const float* __restrict__ gb) {
    extern __shared__ float sm[];
    float* Xhi = sm;            float* Xlo = sm + 4352;
    float* Whi = sm + 8704;     float* Wlo = sm + 13056;
    int hop = blockIdx.z, y = blockIdx.y;
    const float* Mh  = mem + (size_t)hop*BNE;
    const float* Mh1 = mem + (size_t)(hop+1)*BNE;
    const float* Wh  = gw + (size_t)hop*7*4096;
    const float *X, *W, *bias = nullptr; float* out;
    if (y == 0)      { X = Mh;  W = sentw + (size_t)hop*4096; out = d_keysw + (size_t)hop*BNE; }
    else if (y == 1) { X = Mh1; W = Wh; bias = gb + hop*64;   out = d_base  + (size_t)hop*BNE; }
    else             { X = Mh1; W = Wh + (size_t)(y-1)*4096;  out = d_t6 + ((size_t)hop*6 + (y-2))*BNE; }

    int tid = threadIdx.x;
    int rbase = blockIdx.x*64;
    const int R = NNODE;
    for (int idx = tid; idx < 4096; idx += 256) {
        int k = idx >> 6, n = idx & 63;
        float hi, lo; split_tf32(W[idx], hi, lo);
        Whi[n*68 + k] = hi; Wlo[n*68 + k] = lo;
    }
    for (int idx = tid; idx < 4096; idx += 256) {
        int r = idx >> 6, e = idx & 63;
        int rg = rbase + r;
        float v = (rg < R) ? X[(size_t)rg*64 + e] : 0.f;
        float hi, lo; split_tf32(v, hi, lo);
        Xhi[r*68 + e] = hi; Xlo[r*68 + e] = lo;
    }
    __syncthreads();
    int warp = tid >> 5, lane = tid & 31;
    int wm = warp >> 1, wn = warp & 1;
    int ra = wm*16 + (lane >> 2);
    float acc[4][4] = {};
    #pragma unroll
    for (int k8 = 0; k8 < 8; k8++) {
        int e = k8*8 + (lane & 3);
        float ah[4], al[4];
        ah[0] = Xhi[ra*68 + e];     ah[1] = Xhi[(ra+8)*68 + e];
        ah[2] = Xhi[ra*68 + e + 4]; ah[3] = Xhi[(ra+8)*68 + e + 4];
        al[0] = Xlo[ra*68 + e];     al[1] = Xlo[(ra+8)*68 + e];
        al[2] = Xlo[ra*68 + e + 4]; al[3] = Xlo[(ra+8)*68 + e + 4];
        #pragma unroll
        for (int ns = 0; ns < 4; ns++) {
            int nb = wn*32 + ns*8 + (lane >> 2);
            mma3(acc[ns], ah, al, Whi[nb*68 + e], Whi[nb*68 + e + 4],
                                  Wlo[nb*68 + e], Wlo[nb*68 + e + 4]);
        }
    }
    int r1 = rbase + wm*16 + (lane >> 2);
    #pragma unroll
    for (int ns = 0; ns < 4; ns++) {
        int c = wn*32 + ns*8 + (lane & 3)*2;
        float b0 = bias ? bias[c] : 0.f;
        float b1 = bias ? bias[c+1] : 0.f;
        if (r1 < R) {
            out[(size_t)r1*64 + c]     = acc[ns][0] + b0;
            out[(size_t)r1*64 + c + 1] = acc[ns][1] + b1;
        }
        if (r1 + 8 < R) {
            out[(size_t)(r1+8)*64 + c]     = acc[ns][2] + b0;
            out[(size_t)(r1+8)*64 + c + 1] = acc[ns][3] + b1;
        }
    }
}

// ---------------- einsum (2-MMA, A staged once per 2 b's): grid (6, 16, 9) ------------
__global__ void __launch_bounds__(256) k_einsum_all(const float* __restrict__ supports, int phase) {
    extern __shared__ float sm[];
    float* Ahi = sm;          // 64*68
    float* Bhi = sm + 4352;   // 64*68
    float* Blo = sm + 8704;   // 64*68
    int z = blockIdx.z;
    int hop = z/3, s = z%3;
    const float* adj = (s < 2) ? supports + (size_t)s*Nn*Nn : d_adp;
    const float *Xb, *addb; float* outb_;
    if (phase == 0) {
        Xb   = d_t6 + ((size_t)hop*6 + 2*s + 1)*BNE;
        addb = d_t6 + ((size_t)hop*6 + 2*s)*BNE;
        outb_ = d_t3b + ((size_t)hop*3 + s)*BNE;
    } else {
        Xb   = d_t3b + ((size_t)hop*3 + s)*BNE;
        addb = nullptr;
        outb_ = d_yp + ((size_t)hop*3 + s)*BNE;
    }
    int tid = threadIdx.x;
    int b0 = blockIdx.y*2;
    int ng = blockIdx.x*64;
    int warp = tid >> 5, lane = tid & 31;
    int wm = warp >> 1, wn = warp & 1;
    int ra = wm*16 + (lane >> 2);
    float acc[2][4][4] = {};
    for (int mc = 0; mc < 384; mc += 64) {
        __syncthreads();
        for (int idx = tid; idx < 4096; idx += 256) {
            int i = idx >> 6, j = idx & 63;
            int nr = ng + i, mm = mc + j;
            float v = (nr < Nn && mm < Nn) ? adj[(size_t)nr*Nn + mm] : 0.f;
            Ahi[i*68 + j] = tf32r(v);
        }
        #pragma unroll
        for (int q = 0; q < 2; q++) {
            __syncthreads();
            const float* X = Xb + (size_t)(b0 + q)*Nn*64;
            for (int idx = tid; idx < 4096; idx += 256) {
                int k = idx >> 6, e = idx & 63;
                int mm = mc + k;
                float v = (mm < Nn) ? X[(size_t)mm*64 + e] : 0.f;
                float hi, lo; split_tf32(v, hi, lo);
                Bhi[e*68 + k] = hi; Blo[e*68 + k] = lo;
            }
            __syncthreads();
            #pragma unroll
            for (int k8 = 0; k8 < 8; k8++) {
                int m = k8*8 + (lane & 3);
                float a0 = Ahi[ra*68 + m];
                float a1 = Ahi[(ra+8)*68 + m];
                float a2 = Ahi[ra*68 + m + 4];
                float a3 = Ahi[(ra+8)*68 + m + 4];
                #pragma unroll
                for (int ns = 0; ns < 4; ns++) {
                    int nb = wn*32 + ns*8 + (lane >> 2);
                    mma8(acc[q][ns], a0, a1, a2, a3, Bhi[nb*68 + m], Bhi[nb*68 + m + 4]);
                    mma8(acc[q][ns], a0, a1, a2, a3, Blo[nb*68 + m], Blo[nb*68 + m + 4]);
                }
            }
        }
    }
    int r1 = ng + wm*16 + (lane >> 2);
    #pragma unroll
    for (int q = 0; q < 2; q++) {
        int b = b0 + q;
        #pragma unroll
        for (int ns = 0; ns < 4; ns++) {
            int e = wn*32 + ns*8 + (lane & 3)*2;
            #pragma unroll
            for (int half = 0; half < 2; half++) {
                int nr = r1 + half*8;
                if (nr < Nn) {
                    size_t g = (size_t)b*Nn*64 + (size_t)nr*64 + e;
                    float v0 = acc[q][ns][half*2], v1 = acc[q][ns][half*2+1];
                    if (addb) { v0 += addb[g]; v1 += addb[g+1]; }
                    outb_[g] = v0; outb_[g+1] = v1;
                }
            }
        }
    }
}

// ---------------- fragment permutes (packed float4: pair of ns groups) ----------------
__global__ void k_permK(const float* __restrict__ mem) {
    int hop = blockIdx.y;
    int b = blockIdx.x / 6, c = blockIdx.x % 6;
    const float* K = mem + (size_t)hop*BNE + (size_t)b*Nn*64;
    float4* out = d_Kf4 + (size_t)hop*FRAG4_PER_HOP + (size_t)(b*6 + c)*FRAG4_PER_BC;
    for (int idx = threadIdx.x; idx < FRAG4_PER_BC; idx += 256) {
        int pair = idx >> 8, k8 = (idx >> 5) & 7, lane = idx & 31;
        int kk0 = c*64 + (pair*2)*8 + (lane >> 2);
        int kk1 = kk0 + 8;
        int e = k8*8 + (lane & 3);
        float x = 0.f, y = 0.f, zz = 0.f, w = 0.f;
        if (kk0 < Nn) { x = K[(size_t)kk0*64 + e]; y = K[(size_t)kk0*64 + e + 4]; }
        if (kk1 < Nn) { zz = K[(size_t)kk1*64 + e]; w = K[(size_t)kk1*64 + e + 4]; }
        out[idx] = make_float4(tf32r(x), tf32r(y), tf32r(zz), tf32r(w));
    }
}

__global__ void k_permV() {
    int hop = blockIdx.y;
    int b = blockIdx.x / 6, c = blockIdx.x % 6;
    const float* Y0 = d_yp + ((size_t)hop*3 + 0)*BNE + (size_t)b*Nn*64;
    const float* Y1 = d_yp + ((size_t)hop*3 + 1)*BNE + (size_t)b*Nn*64;
    const float* Y2 = d_yp + ((size_t)hop*3 + 2)*BNE + (size_t)b*Nn*64;
    float4* out = d_Vf4 + (size_t)hop*FRAG4_PER_HOP + (size_t)(b*6 + c)*FRAG4_PER_BC;
    for (int idx = threadIdx.x; idx < FRAG4_PER_BC; idx += 256) {
        int pair = idx >> 8, k8 = (idx >> 5) & 7, lane = idx & 31;
        int e0 = (pair*2)*8 + (lane >> 2);
        int e1 = e0 + 8;
        int kk = c*64 + k8*8 + (lane & 3);
        float x = 0.f, y = 0.f, zz = 0.f, w = 0.f;
        if (kk < Nn) {
            size_t g = (size_t)kk*64;
            x  = Y0[g + e0] + Y1[g + e0] + Y2[g + e0];
            zz = Y0[g + e1] + Y1[g + e1] + Y2[g + e1];
        }
        if (kk + 4 < Nn) {
            size_t g = (size_t)(kk+4)*64;
            y = Y0[g + e0] + Y1[g + e0] + Y2[g + e0];
            w = Y0[g + e1] + Y1[g + e1] + Y2[g + e1];
        }
        out[idx] = make_float4(tf32r(x), tf32r(y), tf32r(zz), tf32r(w));
    }
}

// ---------------- GRU step: 32 rows/block, 325 blocks, 192 threads ----------------
__global__ void k_gru(const float* __restrict__ wih, const float* __restrict__ whh,
                      const float* __restrict__ bih, const float* __restrict__ bhh) {
    extern __shared__ float sm[];
    float* hs  = sm;                 // 32*64
    float* Wt  = sm + 2048;          // 64*193
    float* ghs = Wt + 64*193;        // 32*192
    int tid = threadIdx.x;           // 192
    int g0 = blockIdx.x*32;
    for (int idx = tid; idx < 192*64; idx += 192) {
        int j = idx >> 6, k = idx & 63;
        Wt[k*193 + j] = whh[idx];
    }
    for (int idx = tid; idx < 2048; idx += 192) hs[idx] = d_h[(size_t)g0*64 + idx];
    __syncthreads();
    float acc[32] = {};
    const float4* hs4 = reinterpret_cast<const float4*>(hs);
    #pragma unroll
    for (int kq = 0; kq < 16; kq++) {
        float w0 = Wt[(4*kq+0)*193 + tid];
        float w1 = Wt[(4*kq+1)*193 + tid];
        float w2 = Wt[(4*kq+2)*193 + tid];
        float w3 = Wt[(4*kq+3)*193 + tid];
        #pragma unroll
        for (int i = 0; i < 32; i++) {
            float4 hv = hs4[i*16 + kq];
            acc[i] += hv.x*w0 + hv.y*w1 + hv.z*w2 + hv.w*w3;
        }
    }
    float bj = bhh[tid];
    #pragma unroll
    for (int i = 0; i < 32; i++) ghs[i*192 + tid] = acc[i] + bj;
    __syncthreads();
    for (int idx = tid; idx < 2048; idx += 192) {
        int i = idx >> 6, e = idx & 63;
        int g = g0 + i;
        float pv  = d_prev[g];
        float gir = pv*wih[e]      + bih[e];
        float giz = pv*wih[64+e]   + bih[64+e];
        float gin = pv*wih[128+e]  + bih[128+e];
        float ghr = ghs[i*192 + e];
        float ghz = ghs[i*192 + 64 + e];
        float ghn = ghs[i*192 + 128 + e];
        float r = 1.f/(1.f + __expf(-(gir+ghr)));
        float z = 1.f/(1.f + __expf(-(giz+ghz)));
        float nv = tanhf(gin + r*ghn);
        float hold = hs[idx];
        float hn = (1.f - z)*nv + z*hold;
        d_h[(size_t)g*64 + e] = hn;
        d_u[(size_t)g*64 + e] = hn;
    }
    if (tid < 32) d_acc[g0 + tid] = 0.f;
}

// ---------------- attention per hop: 32 q-rows/block, grid (11, 32) ----------------
// pass 1: 2 MMAs ((Q_hi + Q_lo) x K_tf32); pass 3: 1 MMA (P_tf32 x V_tf32).
// K/V fragments packed float4: one LDG.128 serves both ns slices.
__global__ void __launch_bounds__(256)
k_attn(const float4* __restrict__ Kf, const float4* __restrict__ Vf,
       const float* __restrict__ base, const float* __restrict__ ksw, int buf) {
    extern __shared__ float sm[];
    float* Qhi  = sm;
    float* Qlo  = sm + 2176;
    float* Ssm  = sm + 4352;              // 32 x 332
    float* invs = sm + 4352 + 10624;      // 32
    int tid = threadIdx.x;                // 256
    int b = blockIdx.y;
    int q0 = blockIdx.x*32;
    int warp = tid >> 5, lane = tid & 31;
    int wm = warp >> 2, wn = warp & 3;
    const size_t bb = (size_t)b*Nn*64;

    for (int idx = tid; idx < 2048; idx += 256) {
        int r = idx >> 6, e = idx & 63;
        int qg = q0 + r;
        float v = (qg < Nn) ? d_u[bb + (size_t)qg*64 + e] : 0.f;
        float hi, lo; split_tf32(v, hi, lo);
        Qhi[r*68 + e] = hi; Qlo[r*68 + e] = lo;
    }
    #pragma unroll
    for (int r = warp*4; r < warp*4 + 4; r++) {
        int qg = q0 + r;
        if (qg < Nn) {
            const float* up = d_u + bb + (size_t)qg*64;
            const float* kp = ksw + bb + (size_t)qg*64;
            float s = up[lane]*kp[lane] + up[32+lane]*kp[32+lane];
            #pragma unroll
            for (int o = 16; o > 0; o >>= 1) s += __shfl_xor_sync(0xffffffffu, s, o);
            if (lane == 0) d_sent[b*Nn + qg] = s*SCALE_INV;
        }
    }
    __syncthreads();

    int ra = wm*16 + (lane >> 2);
    const float4* Kfb = Kf + (size_t)b*6*FRAG4_PER_BC;

    // ---- pass 1: scores = Q K^T / 8 (2 MMAs, one LDG.128 per k8) ----
    for (int c = 0; c < 6; c++) {
        float acc[2][4] = {};
        const float4* Kfc = Kfb + c*FRAG4_PER_BC;
        #pragma unroll
        for (int k8 = 0; k8 < 8; k8++) {
            int e = k8*8 + (lane & 3);
            float ah0 = Qhi[ra*68 + e],     ah1 = Qhi[(ra+8)*68 + e];
            float ah2 = Qhi[ra*68 + e + 4], ah3 = Qhi[(ra+8)*68 + e + 4];
            float al0 = Qlo[ra*68 + e],     al1 = Qlo[(ra+8)*68 + e];
            float al2 = Qlo[ra*68 + e + 4], al3 = Qlo[(ra+8)*68 + e + 4];
            float4 f = Kfc[wn*256 + k8*32 + lane];
            mma8(acc[0], ah0, ah1, ah2, ah3, f.x, f.y);
            mma8(acc[0], al0, al1, al2, al3, f.x, f.y);
            mma8(acc[1], ah0, ah1, ah2, ah3, f.z, f.w);
            mma8(acc[1], al0, al1, al2, al3, f.z, f.w);
        }
        #pragma unroll
        for (int ns = 0; ns < 2; ns++) {
            int key = c*64 + (wn*2 + ns)*8 + (lane & 3)*2;
            if (key < Nn) {
                Ssm[ra*332 + key]     = acc[ns][0]*SCALE_INV;
                Ssm[(ra+8)*332 + key] = acc[ns][2]*SCALE_INV;
            }
            if (key + 1 < Nn) {
                Ssm[ra*332 + key + 1]     = acc[ns][1]*SCALE_INV;
                Ssm[(ra+8)*332 + key + 1] = acc[ns][3]*SCALE_INV;
            }
        }
    }
    __syncthreads();

    // ---- pass 2: softmax rows (unnormalized exp) ----
    #pragma unroll
    for (int r = warp*4; r < warp*4 + 4; r++) {
        float mx = -1e30f;
        for (int m = lane; m < Nn; m += 32) mx = fmaxf(mx, Ssm[r*332 + m]);
        #pragma unroll
        for (int o = 16; o > 0; o >>= 1) mx = fmaxf(mx, __shfl_xor_sync(0xffffffffu, mx, o));
        float sum = 0.f;
        for (int m = lane; m < Nn; m += 32) {
            float ev = __expf(Ssm[r*332 + m] - mx);
            Ssm[r*332 + m] = ev;
            sum += ev;
        }
        #pragma unroll
        for (int o = 16; o > 0; o >>= 1) sum += __shfl_xor_sync(0xffffffffu, sum, o);
        if (lane == 0) invs[r] = 1.f/sum;
    }
    __syncthreads();

    // ---- pass 3: O = P_tf32 @ V_hi (one LDG.128 serves both ns MMAs) ----
    float oacc[2][4] = {};
    const float4* Vfb = Vf + (size_t)b*6*FRAG4_PER_BC;
    for (int c = 0; c < 6; c++) {
        const float4* Vfc = Vfb + c*FRAG4_PER_BC;
        #pragma unroll
        for (int k8 = 0; k8 < 8; k8++) {
            int m = c*64 + k8*8 + (lane & 3);
            float p0 = (m < Nn)     ? Ssm[ra*332 + m]         : 0.f;
            float p1 = (m < Nn)     ? Ssm[(ra+8)*332 + m]     : 0.f;
            float p2 = (m + 4 < Nn) ? Ssm[ra*332 + m + 4]     : 0.f;
            float p3 = (m + 4 < Nn) ? Ssm[(ra+8)*332 + m + 4] : 0.f;
            float a0 = tf32r(p0), a1 = tf32r(p1), a2 = tf32r(p2), a3 = tf32r(p3);
            float4 f = Vfc[wn*256 + k8*32 + lane];
            mma8(oacc[0], a0, a1, a2, a3, f.x, f.y);
            mma8(oacc[1], a0, a1, a2, a3, f.z, f.w);
        }
    }

    // ---- epilogue: opre = oacc*inv + base; BN partial sums ----
    __syncthreads();
    float* rowsum = Qhi;
    float* rowsq  = Qhi + 32;
    if (tid < 64) Qhi[tid] = 0.f;
    __syncthreads();

    float iv1 = invs[ra], iv2 = invs[ra + 8];
    float s1 = 0.f, q1 = 0.f, s2 = 0.f, q2 = 0.f;
    int qg1 = q0 + ra, qg2 = qg1 + 8;
    #pragma unroll
    for (int ns = 0; ns < 2; ns++) {
        int e = (wn*2 + ns)*8 + (lane & 3)*2;
        if (qg1 < Nn) {
            size_t g = bb + (size_t)qg1*64 + e;
            float v0 = oacc[ns][0]*iv1 + base[g];
            float v1 = oacc[ns][1]*iv1 + base[g+1];
            d_opre[g] = v0; d_opre[g+1] = v1;
            s1 += v0 + v1; q1 += v0*v0 + v1*v1;
        }
        if (qg2 < Nn) {
            size_t g = bb + (size_t)qg2*64 + e;
            float v2 = oacc[ns][2]*iv2 + base[g];
            float v3 = oacc[ns][3]*iv2 + base[g+1];
            d_opre[g] = v2; d_opre[g+1] = v3;
            s2 += v2 + v3; q2 += v2*v2 + v3*v3;
        }
    }
    #pragma unroll
    for (int o = 1; o < 4; o <<= 1) {
        s1 += __shfl_xor_sync(0xffffffffu, s1, o);
        q1 += __shfl_xor_sync(0xffffffffu, q1, o);
        s2 += __shfl_xor_sync(0xffffffffu, s2, o);
        q2 += __shfl_xor_sync(0xffffffffu, q2, o);
    }
    if ((lane & 3) == 0) {
        atomicAdd(&rowsum[ra], s1);     atomicAdd(&rowsq[ra], q1);
        atomicAdd(&rowsum[ra + 8], s2); atomicAdd(&rowsq[ra + 8], q2);
    }
    __syncthreads();
    if (tid < 32) {
        int qg = q0 + tid;
        if (qg < Nn) {
            atomicAdd(&d_bnsum[buf][qg], rowsum[tid]);
            atomicAdd(&d_bnsq[buf][qg],  rowsq[tid]);
        }
    }
}

// ---------------- BN apply + u update + sentinel-weighted output accum ----------------
__global__ void k_apply(const float* __restrict__ gamma, const float* __restrict__ beta,
                        const float* __restrict__ outw, const float* __restrict__ outb,
                        float* __restrict__ dout, int step, int lasthop, int buf) {
    int lane = threadIdx.x & 31;
    int g = blockIdx.x*8 + (threadIdx.x >> 5);
    if (blockIdx.x == 0) {
        for (int i = threadIdx.x; i < Nn; i += 256) {
            d_bnsum[buf^1][i] = 0.f;
            d_bnsq[buf^1][i]  = 0.f;
        }
    }
    if (g >= NNODE) return;
    int b = g / Nn, n = g % Nn;
    float mu = d_bnsum[buf][n]*(1.f/2048.f);
    float var = d_bnsq[buf][n]*(1.f/2048.f) - mu*mu;
    float rs = rsqrtf(var + 1e-5f);
    float gm = gamma[n]*rs, bt = beta[n];
    float v1 = (d_opre[(size_t)g*64 + lane]      - mu)*gm + bt;
    float v2 = (d_opre[(size_t)g*64 + 32 + lane] - mu)*gm + bt;
    d_u[(size_t)g*64 + lane]      += v1;
    d_u[(size_t)g*64 + 32 + lane] += v2;
    float dv = v1*outw[lane] + v2*outw[32 + lane];
    #pragma unroll
    for (int o = 16; o > 0; o >>= 1) dv += __shfl_xor_sync(0xffffffffu, dv, o);
    if (lane == 0) {
        float a = d_acc[g] + d_sent[g]*dv;
        d_acc[g] = a;
        if (lasthop) {
            float val = a + outb[0];
            dout[(size_t)b*St*Nn + (size_t)step*Nn + n] = val;
            d_prev[g] = val;
        }
    }
}

// ---------------- host orchestration ----------------
extern "C" void kernel_launch(void* const* d_in, const int* in_sizes, int n_in,
                              void* d_out, int out_size) {
    const float* hidden   = (const float*)d_in[0];
    const float* supports = (const float*)d_in[1];
    const float* memory   = (const float*)d_in[3];
    const float* nv1      = (const float*)d_in[4];
    const float* nv2      = (const float*)d_in[5];
    const float* wih      = (const float*)d_in[6];
    const float* whh      = (const float*)d_in[7];
    const float* bih      = (const float*)d_in[8];
    const float* bhh      = (const float*)d_in[9];
    const float* sentw    = (const float*)d_in[10];
    const float* gamma    = (const float*)d_in[11];
    const float* beta     = (const float*)d_in[12];
    const float* gw       = (const float*)d_in[13];
    const float* gb       = (const float*)d_in[14];
    const float* outw     = (const float*)d_in[15];
    const float* outb     = (const float*)d_in[16];
    float* dout = (float*)d_out;

    void* pv;
    float *p_keysw, *p_base, *p_h, *p_prev, *p_bnsum, *p_bnsq;
    float4 *p_Kf4, *p_Vf4;
    cudaGetSymbolAddress(&pv, d_keysw); p_keysw = (float*)pv;
    cudaGetSymbolAddress(&pv, d_base);  p_base  = (float*)pv;
    cudaGetSymbolAddress(&pv, d_h);     p_h     = (float*)pv;
    cudaGetSymbolAddress(&pv, d_prev);  p_prev  = (float*)pv;
    cudaGetSymbolAddress(&pv, d_bnsum); p_bnsum = (float*)pv;
    cudaGetSymbolAddress(&pv, d_bnsq);  p_bnsq  = (float*)pv;
    cudaGetSymbolAddress(&pv, d_Kf4);   p_Kf4   = (float4*)pv;
    cudaGetSymbolAddress(&pv, d_Vf4);   p_Vf4   = (float4*)pv;

    const int SMEM_MM   = 17408*4;                       // 69632
    const int SMEM_EIN  = 13056*4;                       // 52224
    const int SMEM_ATTN = 15008*4;                       // 60032
    const int SMEM_GRU  = (2048 + 64*193 + 32*192)*4;    // 82176
    cudaFuncSetAttribute(k_gru,        cudaFuncAttributeMaxDynamicSharedMemorySize, SMEM_GRU);
    cudaFuncSetAttribute(k_attn,       cudaFuncAttributeMaxDynamicSharedMemorySize, SMEM_ATTN);
    cudaFuncSetAttribute(k_matmul_all, cudaFuncAttributeMaxDynamicSharedMemorySize, SMEM_MM);
    cudaFuncSetAttribute(k_einsum_all, cudaFuncAttributeMaxDynamicSharedMemorySize, SMEM_EIN);

    cudaMemcpyAsync(p_h, hidden, (size_t)BNE*sizeof(float), cudaMemcpyDeviceToDevice, 0);
    cudaMemsetAsync(p_prev, 0, (size_t)NNODE*sizeof(float), 0);
    cudaMemsetAsync(p_bnsum, 0, 2*Nn*sizeof(float), 0);
    cudaMemsetAsync(p_bnsq,  0, 2*Nn*sizeof(float), 0);

    // ---- step-invariant precompute ----
    k_adp<<<Nn, 128>>>(nv1, nv2);
    k_matmul_all<<<dim3(163, 8, 3), 256, SMEM_MM>>>(memory, sentw, gw, gb);
    k_einsum_all<<<dim3(6, 16, 9), 256, SMEM_EIN>>>(supports, 0);
    k_einsum_all<<<dim3(6, 16, 9), 256, SMEM_EIN>>>(supports, 1);
    k_permK<<<dim3(192, 3), 256>>>(memory);
    k_permV<<<dim3(192, 3), 256>>>();

    // ---- sequential scan ----
    for (int st = 0; st < St; st++) {
        k_gru<<<325, 192, SMEM_GRU>>>(wih, whh, bih, bhh);
        for (int hop = 0; hop < NHOP; hop++) {
            int idx = st*NHOP + hop;
            int buf = idx & 1;
            k_attn<<<dim3(11, Bb), 256, SMEM_ATTN>>>(p_Kf4 + (size_t)hop*FRAG4_PER_HOP,
                                                     p_Vf4 + (size_t)hop*FRAG4_PER_HOP,
                                                     p_base + (size_t)hop*BNE,
                                                     p_keysw + (size_t)hop*BNE,
                                                     buf);
            k_apply<<<1300, 256>>>(gamma + hop*Nn, beta + hop*Nn, outw, outb,
                                   dout, st, hop == 2 ? 1 : 0, buf);
        }
    }
}

// round 15
// speedup vs baseline: 1.0874x; 1.0129x over previous
#include <cuda_runtime.h>
#include <math.h>

#define Bb 32
#define Nn 325
#define Ee 64
#define St 12
#define NHOP 3
#define NNODE (Bb*Nn)        // 10400
#define BNE (Bb*Nn*Ee)       // 665600
#define SCALE_INV 0.125f
#define FRAG4_PER_BC 1024    // 4 pairs * 8 k8 * 32 lanes (float4 each)
#define FRAG4_PER_HOP (Bb*6*FRAG4_PER_BC)

// ---------------- scratch (device globals; no allocation allowed) ----------------
__device__ float d_adp[Nn*Nn];
__device__ float d_keysw[NHOP*BNE];
__device__ float d_base [NHOP*BNE];
__device__ float d_t6 [NHOP*6*BNE];
__device__ float d_t3b[NHOP*3*BNE];
__device__ float d_yp [NHOP*3*BNE];
__device__ float4 d_Kf4[NHOP*FRAG4_PER_HOP];
__device__ float4 d_Vf4[NHOP*FRAG4_PER_HOP];
__device__ float d_h[BNE], d_u[BNE], d_opre[BNE];
__device__ float d_prev[NNODE], d_sent[NNODE], d_acc[NNODE];
__device__ float d_bnsum[2][Nn], d_bnsq[2][Nn];

// ---------------- tf32 helpers ----------------
__device__ __forceinline__ void split_tf32(float x, float& hi, float& lo) {
    unsigned h; asm("cvt.rna.tf32.f32 %0, %1;" : "=r"(h) : "f"(x));
    float hf = __uint_as_float(h);
    unsigned l; asm("cvt.rna.tf32.f32 %0, %1;" : "=r"(l) : "f"(x - hf));
    hi = hf; lo = __uint_as_float(l);
}
__device__ __forceinline__ float tf32r(float x) {
    unsigned h; asm("cvt.rna.tf32.f32 %0, %1;" : "=r"(h) : "f"(x));
    return __uint_as_float(h);
}

__device__ __forceinline__ void mma8(float* d,
        float a0, float a1, float a2, float a3, float b0, float b1) {
    asm volatile(
        "mma.sync.aligned.m16n8k8.row.col.f32.tf32.tf32.f32 "
        "{%0,%1,%2,%3},{%4,%5,%6,%7},{%8,%9},{%0,%1,%2,%3};"
        : "+f"(d[0]), "+f"(d[1]), "+f"(d[2]), "+f"(d[3])
        : "r"(__float_as_uint(a0)), "r"(__float_as_uint(a1)),
          "r"(__float_as_uint(a2)), "r"(__float_as_uint(a3)),
          "r"(__float_as_uint(b0)), "r"(__float_as_uint(b1)));
}

__device__ __forceinline__ void mma3(float* d,
        const float* ah, const float* al, float bh0, float bh1, float bl0, float bl1) {
    mma8(d, ah[0], ah[1], ah[2], ah[3], bh0, bh1);
    mma8(d, ah[0], ah[1], ah[2], ah[3], bl0, bl1);
    mma8(d, al[0], al[1], al[2], al[3], bh0, bh1);
}

// ---------------- adaptive adjacency ----------------
__global__ void k_adp(const float* __restrict__ nv1, const float* __restrict__ nv2) {
    __shared__ float nv1s[64];
    __shared__ float vals[Nn];
    __shared__ float red[128];
    int n = blockIdx.x, tid = threadIdx.x;
    if (tid < 64) nv1s[tid] = nv1[n*64 + tid];
    __syncthreads();
    float lmax = -1e30f;
    for (int m = tid; m < Nn; m += 128) {
        const float* p = nv2 + m*64;
        float dot = 0.f;
        #pragma unroll
        for (int k = 0; k < 64; k++) dot += nv1s[k]*p[k];
        float v = fmaxf(dot, 0.f);
        vals[m] = v;
        lmax = fmaxf(lmax, v);
    }
    red[tid] = lmax; __syncthreads();
    for (int s = 64; s > 0; s >>= 1) { if (tid < s) red[tid] = fmaxf(red[tid], red[tid+s]); __syncthreads(); }
    float mx = red[0]; __syncthreads();
    float lsum = 0.f;
    for (int m = tid; m < Nn; m += 128) {
        float e = __expf(vals[m] - mx);
        vals[m] = e; lsum += e;
    }
    red[tid] = lsum; __syncthreads();
    for (int s = 64; s > 0; s >>= 1) { if (tid < s) red[tid] += red[tid+s]; __syncthreads(); }
    float inv = 1.f/red[0];
    for (int m = tid; m < Nn; m += 128) d_adp[n*Nn + m] = vals[m]*inv;
}

// ---------------- all hop projections (full 3xTF32): grid (163, 8, 3) ----------------
__global__ void __launch_bounds__(256) k_matmul_all(const float* __restrict__ mem, const float* __restrict__ sentw,
                             const float* __restrict__ gw, const float* __restrict__ gb) {
    extern __shared__ float sm[];
    float* Xhi = sm;            float* Xlo = sm + 4352;
    float* Whi = sm + 8704;     float* Wlo = sm + 13056;
    int hop = blockIdx.z, y = blockIdx.y;
    const float* Mh  = mem + (size_t)hop*BNE;
    const float* Mh1 = mem + (size_t)(hop+1)*BNE;
    const float* Wh  = gw + (size_t)hop*7*4096;
    const float *X, *W, *bias = nullptr; float* out;
    if (y == 0)      { X = Mh;  W = sentw + (size_t)hop*4096; out = d_keysw + (size_t)hop*BNE; }
    else if (y == 1) { X = Mh1; W = Wh; bias = gb + hop*64;   out = d_base  + (size_t)hop*BNE; }
    else             { X = Mh1; W = Wh + (size_t)(y-1)*4096;  out = d_t6 + ((size_t)hop*6 + (y-2))*BNE; }

    int tid = threadIdx.x;
    int rbase = blockIdx.x*64;
    const int R = NNODE;
    for (int idx = tid; idx < 4096; idx += 256) {
        int k = idx >> 6, n = idx & 63;
        float hi, lo; split_tf32(W[idx], hi, lo);
        Whi[n*68 + k] = hi; Wlo[n*68 + k] = lo;
    }
    for (int idx = tid; idx < 4096; idx += 256) {
        int r = idx >> 6, e = idx & 63;
        int rg = rbase + r;
        float v = (rg < R) ? X[(size_t)rg*64 + e] : 0.f;
        float hi, lo; split_tf32(v, hi, lo);
        Xhi[r*68 + e] = hi; Xlo[r*68 + e] = lo;
    }
    __syncthreads();
    int warp = tid >> 5, lane = tid & 31;
    int wm = warp >> 1, wn = warp & 1;
    int ra = wm*16 + (lane >> 2);
    float acc[4][4] = {};
    #pragma unroll
    for (int k8 = 0; k8 < 8; k8++) {
        int e = k8*8 + (lane & 3);
        float ah[4], al[4];
        ah[0] = Xhi[ra*68 + e];     ah[1] = Xhi[(ra+8)*68 + e];
        ah[2] = Xhi[ra*68 + e + 4]; ah[3] = Xhi[(ra+8)*68 + e + 4];
        al[0] = Xlo[ra*68 + e];     al[1] = Xlo[(ra+8)*68 + e];
        al[2] = Xlo[ra*68 + e + 4]; al[3] = Xlo[(ra+8)*68 + e + 4];
        #pragma unroll
        for (int ns = 0; ns < 4; ns++) {
            int nb = wn*32 + ns*8 + (lane >> 2);
            mma3(acc[ns], ah, al, Whi[nb*68 + e], Whi[nb*68 + e + 4],
                                  Wlo[nb*68 + e], Wlo[nb*68 + e + 4]);
        }
    }
    int r1 = rbase + wm*16 + (lane >> 2);
    #pragma unroll
    for (int ns = 0; ns < 4; ns++) {
        int c = wn*32 + ns*8 + (lane & 3)*2;
        float b0 = bias ? bias[c] : 0.f;
        float b1 = bias ? bias[c+1] : 0.f;
        if (r1 < R) {
            out[(size_t)r1*64 + c]     = acc[ns][0] + b0;
            out[(size_t)r1*64 + c + 1] = acc[ns][1] + b1;
        }
        if (r1 + 8 < R) {
            out[(size_t)(r1+8)*64 + c]     = acc[ns][2] + b0;
            out[(size_t)(r1+8)*64 + c + 1] = acc[ns][3] + b1;
        }
    }
}

// ---------------- einsum: grid (6, 16, 9) ------------
// phase 0: t3b = t6a + adj_tf32 @ (B_hi + B_lo)   (2 MMAs)
// phase 1: yp  = adj_tf32 @ t3b_tf32              (1 MMA; B_lo dropped — feeds tf32 V chain)
__global__ void __launch_bounds__(256) k_einsum_all(const float* __restrict__ supports, int phase) {
    extern __shared__ float sm[];
    float* Ahi = sm;          // 64*68
    float* Bhi = sm + 4352;   // 64*68
    float* Blo = sm + 8704;   // 64*68 (phase 0 only)
    int z = blockIdx.z;
    int hop = z/3, s = z%3;
    const float* adj = (s < 2) ? supports + (size_t)s*Nn*Nn : d_adp;
    const float *Xb, *addb; float* outb_;
    if (phase == 0) {
        Xb   = d_t6 + ((size_t)hop*6 + 2*s + 1)*BNE;
        addb = d_t6 + ((size_t)hop*6 + 2*s)*BNE;
        outb_ = d_t3b + ((size_t)hop*3 + s)*BNE;
    } else {
        Xb   = d_t3b + ((size_t)hop*3 + s)*BNE;
        addb = nullptr;
        outb_ = d_yp + ((size_t)hop*3 + s)*BNE;
    }
    int tid = threadIdx.x;
    int b0 = blockIdx.y*2;
    int ng = blockIdx.x*64;
    int warp = tid >> 5, lane = tid & 31;
    int wm = warp >> 1, wn = warp & 1;
    int ra = wm*16 + (lane >> 2);
    float acc[2][4][4] = {};
    for (int mc = 0; mc < 384; mc += 64) {
        __syncthreads();
        for (int idx = tid; idx < 4096; idx += 256) {
            int i = idx >> 6, j = idx & 63;
            int nr = ng + i, mm = mc + j;
            float v = (nr < Nn && mm < Nn) ? adj[(size_t)nr*Nn + mm] : 0.f;
            Ahi[i*68 + j] = tf32r(v);
        }
        #pragma unroll
        for (int q = 0; q < 2; q++) {
            __syncthreads();
            const float* X = Xb + (size_t)(b0 + q)*Nn*64;
            if (phase == 0) {
                for (int idx = tid; idx < 4096; idx += 256) {
                    int k = idx >> 6, e = idx & 63;
                    int mm = mc + k;
                    float v = (mm < Nn) ? X[(size_t)mm*64 + e] : 0.f;
                    float hi, lo; split_tf32(v, hi, lo);
                    Bhi[e*68 + k] = hi; Blo[e*68 + k] = lo;
                }
            } else {
                for (int idx = tid; idx < 4096; idx += 256) {
                    int k = idx >> 6, e = idx & 63;
                    int mm = mc + k;
                    float v = (mm < Nn) ? X[(size_t)mm*64 + e] : 0.f;
                    Bhi[e*68 + k] = tf32r(v);
                }
            }
            __syncthreads();
            #pragma unroll
            for (int k8 = 0; k8 < 8; k8++) {
                int m = k8*8 + (lane & 3);
                float a0 = Ahi[ra*68 + m];
                float a1 = Ahi[(ra+8)*68 + m];
                float a2 = Ahi[ra*68 + m + 4];
                float a3 = Ahi[(ra+8)*68 + m + 4];
                #pragma unroll
                for (int ns = 0; ns < 4; ns++) {
                    int nb = wn*32 + ns*8 + (lane >> 2);
                    mma8(acc[q][ns], a0, a1, a2, a3, Bhi[nb*68 + m], Bhi[nb*68 + m + 4]);
                    if (phase == 0)
                        mma8(acc[q][ns], a0, a1, a2, a3, Blo[nb*68 + m], Blo[nb*68 + m + 4]);
                }
            }
        }
    }
    int r1 = ng + wm*16 + (lane >> 2);
    #pragma unroll
    for (int q = 0; q < 2; q++) {
        int b = b0 + q;
        #pragma unroll
        for (int ns = 0; ns < 4; ns++) {
            int e = wn*32 + ns*8 + (lane & 3)*2;
            #pragma unroll
            for (int half = 0; half < 2; half++) {
                int nr = r1 + half*8;
                if (nr < Nn) {
                    size_t g = (size_t)b*Nn*64 + (size_t)nr*64 + e;
                    float v0 = acc[q][ns][half*2], v1 = acc[q][ns][half*2+1];
                    if (addb) { v0 += addb[g]; v1 += addb[g+1]; }
                    outb_[g] = v0; outb_[g+1] = v1;
                }
            }
        }
    }
}

// ---------------- fragment permutes (packed float4: pair of ns groups) ----------------
__global__ void k_permK(const float* __restrict__ mem) {
    int hop = blockIdx.y;
    int b = blockIdx.x / 6, c = blockIdx.x % 6;
    const float* K = mem + (size_t)hop*BNE + (size_t)b*Nn*64;
    float4* out = d_Kf4 + (size_t)hop*FRAG4_PER_HOP + (size_t)(b*6 + c)*FRAG4_PER_BC;
    for (int idx = threadIdx.x; idx < FRAG4_PER_BC; idx += 256) {
        int pair = idx >> 8, k8 = (idx >> 5) & 7, lane = idx & 31;
        int kk0 = c*64 + (pair*2)*8 + (lane >> 2);
        int kk1 = kk0 + 8;
        int e = k8*8 + (lane & 3);
        float x = 0.f, y = 0.f, zz = 0.f, w = 0.f;
        if (kk0 < Nn) { x = K[(size_t)kk0*64 + e]; y = K[(size_t)kk0*64 + e + 4]; }
        if (kk1 < Nn) { zz = K[(size_t)kk1*64 + e]; w = K[(size_t)kk1*64 + e + 4]; }
        out[idx] = make_float4(tf32r(x), tf32r(y), tf32r(zz), tf32r(w));
    }
}

__global__ void k_permV() {
    int hop = blockIdx.y;
    int b = blockIdx.x / 6, c = blockIdx.x % 6;
    const float* Y0 = d_yp + ((size_t)hop*3 + 0)*BNE + (size_t)b*Nn*64;
    const float* Y1 = d_yp + ((size_t)hop*3 + 1)*BNE + (size_t)b*Nn*64;
    const float* Y2 = d_yp + ((size_t)hop*3 + 2)*BNE + (size_t)b*Nn*64;
    float4* out = d_Vf4 + (size_t)hop*FRAG4_PER_HOP + (size_t)(b*6 + c)*FRAG4_PER_BC;
    for (int idx = threadIdx.x; idx < FRAG4_PER_BC; idx += 256) {
        int pair = idx >> 8, k8 = (idx >> 5) & 7, lane = idx & 31;
        int e0 = (pair*2)*8 + (lane >> 2);
        int e1 = e0 + 8;
        int kk = c*64 + k8*8 + (lane & 3);
        float x = 0.f, y = 0.f, zz = 0.f, w = 0.f;
        if (kk < Nn) {
            size_t g = (size_t)kk*64;
            x  = Y0[g + e0] + Y1[g + e0] + Y2[g + e0];
            zz = Y0[g + e1] + Y1[g + e1] + Y2[g + e1];
        }
        if (kk + 4 < Nn) {
            size_t g = (size_t)(kk+4)*64;
            y = Y0[g + e0] + Y1[g + e0] + Y2[g + e0];
            w = Y0[g + e1] + Y1[g + e1] + Y2[g + e1];
        }
        out[idx] = make_float4(tf32r(x), tf32r(y), tf32r(zz), tf32r(w));
    }
}

// ---------------- GRU step: 32 rows/block, 325 blocks, 192 threads ----------------
__global__ void k_gru(const float* __restrict__ wih, const float* __restrict__ whh,
                      const float* __restrict__ bih, const float* __restrict__ bhh) {
    extern __shared__ float sm[];
    float* hs  = sm;                 // 32*64
    float* Wt  = sm + 2048;          // 64*193
    float* ghs = Wt + 64*193;        // 32*192
    int tid = threadIdx.x;           // 192
    int g0 = blockIdx.x*32;
    for (int idx = tid; idx < 192*64; idx += 192) {
        int j = idx >> 6, k = idx & 63;
        Wt[k*193 + j] = whh[idx];
    }
    for (int idx = tid; idx < 2048; idx += 192) hs[idx] = d_h[(size_t)g0*64 + idx];
    __syncthreads();
    float acc[32] = {};
    const float4* hs4 = reinterpret_cast<const float4*>(hs);
    #pragma unroll
    for (int kq = 0; kq < 16; kq++) {
        float w0 = Wt[(4*kq+0)*193 + tid];
        float w1 = Wt[(4*kq+1)*193 + tid];
        float w2 = Wt[(4*kq+2)*193 + tid];
        float w3 = Wt[(4*kq+3)*193 + tid];
        #pragma unroll
        for (int i = 0; i < 32; i++) {
            float4 hv = hs4[i*16 + kq];
            acc[i] += hv.x*w0 + hv.y*w1 + hv.z*w2 + hv.w*w3;
        }
    }
    float bj = bhh[tid];
    #pragma unroll
    for (int i = 0; i < 32; i++) ghs[i*192 + tid] = acc[i] + bj;
    __syncthreads();
    for (int idx = tid; idx < 2048; idx += 192) {
        int i = idx >> 6, e = idx & 63;
        int g = g0 + i;
        float pv  = d_prev[g];
        float gir = pv*wih[e]      + bih[e];
        float giz = pv*wih[64+e]   + bih[64+e];
        float gin = pv*wih[128+e]  + bih[128+e];
        float ghr = ghs[i*192 + e];
        float ghz = ghs[i*192 + 64 + e];
        float ghn = ghs[i*192 + 128 + e];
        float r = 1.f/(1.f + __expf(-(gir+ghr)));
        float z = 1.f/(1.f + __expf(-(giz+ghz)));
        float nv = tanhf(gin + r*ghn);
        float hold = hs[idx];
        float hn = (1.f - z)*nv + z*hold;
        d_h[(size_t)g*64 + e] = hn;
        d_u[(size_t)g*64 + e] = hn;
    }
    if (tid < 32) d_acc[g0 + tid] = 0.f;
}

// ---------------- attention per hop: 32 q-rows/block, grid (11, 32) (R14 exact) --------
__global__ void __launch_bounds__(256)
k_attn(const float4* __restrict__ Kf, const float4* __restrict__ Vf,
       const float* __restrict__ base, const float* __restrict__ ksw, int buf) {
    extern __shared__ float sm[];
    float* Qhi  = sm;
    float* Qlo  = sm + 2176;
    float* Ssm  = sm + 4352;              // 32 x 332
    float* invs = sm + 4352 + 10624;      // 32
    int tid = threadIdx.x;                // 256
    int b = blockIdx.y;
    int q0 = blockIdx.x*32;
    int warp = tid >> 5, lane = tid & 31;
    int wm = warp >> 2, wn = warp & 3;
    const size_t bb = (size_t)b*Nn*64;

    for (int idx = tid; idx < 2048; idx += 256) {
        int r = idx >> 6, e = idx & 63;
        int qg = q0 + r;
        float v = (qg < Nn) ? d_u[bb + (size_t)qg*64 + e] : 0.f;
        float hi, lo; split_tf32(v, hi, lo);
        Qhi[r*68 + e] = hi; Qlo[r*68 + e] = lo;
    }
    #pragma unroll
    for (int r = warp*4; r < warp*4 + 4; r++) {
        int qg = q0 + r;
        if (qg < Nn) {
            const float* up = d_u + bb + (size_t)qg*64;
            const float* kp = ksw + bb + (size_t)qg*64;
            float s = up[lane]*kp[lane] + up[32+lane]*kp[32+lane];
            #pragma unroll
            for (int o = 16; o > 0; o >>= 1) s += __shfl_xor_sync(0xffffffffu, s, o);
            if (lane == 0) d_sent[b*Nn + qg] = s*SCALE_INV;
        }
    }
    __syncthreads();

    int ra = wm*16 + (lane >> 2);
    const float4* Kfb = Kf + (size_t)b*6*FRAG4_PER_BC;

    // ---- pass 1: scores = Q K^T / 8 (2 MMAs, one LDG.128 per k8) ----
    for (int c = 0; c < 6; c++) {
        float acc[2][4] = {};
        const float4* Kfc = Kfb + c*FRAG4_PER_BC;
        #pragma unroll
        for (int k8 = 0; k8 < 8; k8++) {
            int e = k8*8 + (lane & 3);
            float ah0 = Qhi[ra*68 + e],     ah1 = Qhi[(ra+8)*68 + e];
            float ah2 = Qhi[ra*68 + e + 4], ah3 = Qhi[(ra+8)*68 + e + 4];
            float al0 = Qlo[ra*68 + e],     al1 = Qlo[(ra+8)*68 + e];
            float al2 = Qlo[ra*68 + e + 4], al3 = Qlo[(ra+8)*68 + e + 4];
            float4 f = Kfc[wn*256 + k8*32 + lane];
            mma8(acc[0], ah0, ah1, ah2, ah3, f.x, f.y);
            mma8(acc[0], al0, al1, al2, al3, f.x, f.y);
            mma8(acc[1], ah0, ah1, ah2, ah3, f.z, f.w);
            mma8(acc[1], al0, al1, al2, al3, f.z, f.w);
        }
        #pragma unroll
        for (int ns = 0; ns < 2; ns++) {
            int key = c*64 + (wn*2 + ns)*8 + (lane & 3)*2;
            if (key < Nn) {
                Ssm[ra*332 + key]     = acc[ns][0]*SCALE_INV;
                Ssm[(ra+8)*332 + key] = acc[ns][2]*SCALE_INV;
            }
            if (key + 1 < Nn) {
                Ssm[ra*332 + key + 1]     = acc[ns][1]*SCALE_INV;
                Ssm[(ra+8)*332 + key + 1] = acc[ns][3]*SCALE_INV;
            }
        }
    }
    __syncthreads();

    // ---- pass 2: softmax rows (unnormalized exp) ----
    #pragma unroll
    for (int r = warp*4; r < warp*4 + 4; r++) {
        float mx = -1e30f;
        for (int m = lane; m < Nn; m += 32) mx = fmaxf(mx, Ssm[r*332 + m]);
        #pragma unroll
        for (int o = 16; o > 0; o >>= 1) mx = fmaxf(mx, __shfl_xor_sync(0xffffffffu, mx, o));
        float sum = 0.f;
        for (int m = lane; m < Nn; m += 32) {
            float ev = __expf(Ssm[r*332 + m] - mx);
            Ssm[r*332 + m] = ev;
            sum += ev;
        }
        #pragma unroll
        for (int o = 16; o > 0; o >>= 1) sum += __shfl_xor_sync(0xffffffffu, sum, o);
        if (lane == 0) invs[r] = 1.f/sum;
    }
    __syncthreads();

    // ---- pass 3: O = P_tf32 @ V_hi (one LDG.128 serves both ns MMAs) ----
    float oacc[2][4] = {};
    const float4* Vfb = Vf + (size_t)b*6*FRAG4_PER_BC;
    for (int c = 0; c < 6; c++) {
        const float4* Vfc = Vfb + c*FRAG4_PER_BC;
        #pragma unroll
        for (int k8 = 0; k8 < 8; k8++) {
            int m = c*64 + k8*8 + (lane & 3);
            float p0 = (m < Nn)     ? Ssm[ra*332 + m]         : 0.f;
            float p1 = (m < Nn)     ? Ssm[(ra+8)*332 + m]     : 0.f;
            float p2 = (m + 4 < Nn) ? Ssm[ra*332 + m + 4]     : 0.f;
            float p3 = (m + 4 < Nn) ? Ssm[(ra+8)*332 + m + 4] : 0.f;
            float a0 = tf32r(p0), a1 = tf32r(p1), a2 = tf32r(p2), a3 = tf32r(p3);
            float4 f = Vfc[wn*256 + k8*32 + lane];
            mma8(oacc[0], a0, a1, a2, a3, f.x, f.y);
            mma8(oacc[1], a0, a1, a2, a3, f.z, f.w);
        }
    }

    // ---- epilogue: opre = oacc*inv + base; BN partial sums ----
    __syncthreads();
    float* rowsum = Qhi;
    float* rowsq  = Qhi + 32;
    if (tid < 64) Qhi[tid] = 0.f;
    __syncthreads();

    float iv1 = invs[ra], iv2 = invs[ra + 8];
    float s1 = 0.f, q1 = 0.f, s2 = 0.f, q2 = 0.f;
    int qg1 = q0 + ra, qg2 = qg1 + 8;
    #pragma unroll
    for (int ns = 0; ns < 2; ns++) {
        int e = (wn*2 + ns)*8 + (lane & 3)*2;
        if (qg1 < Nn) {
            size_t g = bb + (size_t)qg1*64 + e;
            float v0 = oacc[ns][0]*iv1 + base[g];
            float v1 = oacc[ns][1]*iv1 + base[g+1];
            d_opre[g] = v0; d_opre[g+1] = v1;
            s1 += v0 + v1; q1 += v0*v0 + v1*v1;
        }
        if (qg2 < Nn) {
            size_t g = bb + (size_t)qg2*64 + e;
            float v2 = oacc[ns][2]*iv2 + base[g];
            float v3 = oacc[ns][3]*iv2 + base[g+1];
            d_opre[g] = v2; d_opre[g+1] = v3;
            s2 += v2 + v3; q2 += v2*v2 + v3*v3;
        }
    }
    #pragma unroll
    for (int o = 1; o < 4; o <<= 1) {
        s1 += __shfl_xor_sync(0xffffffffu, s1, o);
        q1 += __shfl_xor_sync(0xffffffffu, q1, o);
        s2 += __shfl_xor_sync(0xffffffffu, s2, o);
        q2 += __shfl_xor_sync(0xffffffffu, q2, o);
    }
    if ((lane & 3) == 0) {
        atomicAdd(&rowsum[ra], s1);     atomicAdd(&rowsq[ra], q1);
        atomicAdd(&rowsum[ra + 8], s2); atomicAdd(&rowsq[ra + 8], q2);
    }
    __syncthreads();
    if (tid < 32) {
        int qg = q0 + tid;
        if (qg < Nn) {
            atomicAdd(&d_bnsum[buf][qg], rowsum[tid]);
            atomicAdd(&d_bnsq[buf][qg],  rowsq[tid]);
        }
    }
}

// ---------------- BN apply + u update + sentinel-weighted output accum ----------------
__global__ void k_apply(const float* __restrict__ gamma, const float* __restrict__ beta,
                        const float* __restrict__ outw, const float* __restrict__ outb,
                        float* __restrict__ dout, int step, int lasthop, int buf) {
    int lane = threadIdx.x & 31;
    int g = blockIdx.x*8 + (threadIdx.x >> 5);
    if (blockIdx.x == 0) {
        for (int i = threadIdx.x; i < Nn; i += 256) {
            d_bnsum[buf^1][i] = 0.f;
            d_bnsq[buf^1][i]  = 0.f;
        }
    }
    if (g >= NNODE) return;
    int b = g / Nn, n = g % Nn;
    float mu = d_bnsum[buf][n]*(1.f/2048.f);
    float var = d_bnsq[buf][n]*(1.f/2048.f) - mu*mu;
    float rs = rsqrtf(var + 1e-5f);
    float gm = gamma[n]*rs, bt = beta[n];
    float v1 = (d_opre[(size_t)g*64 + lane]      - mu)*gm + bt;
    float v2 = (d_opre[(size_t)g*64 + 32 + lane] - mu)*gm + bt;
    d_u[(size_t)g*64 + lane]      += v1;
    d_u[(size_t)g*64 + 32 + lane] += v2;
    float dv = v1*outw[lane] + v2*outw[32 + lane];
    #pragma unroll
    for (int o = 16; o > 0; o >>= 1) dv += __shfl_xor_sync(0xffffffffu, dv, o);
    if (lane == 0) {
        float a = d_acc[g] + d_sent[g]*dv;
        d_acc[g] = a;
        if (lasthop) {
            float val = a + outb[0];
            dout[(size_t)b*St*Nn + (size_t)step*Nn + n] = val;
            d_prev[g] = val;
        }
    }
}

// ---------------- host orchestration ----------------
extern "C" void kernel_launch(void* const* d_in, const int* in_sizes, int n_in,
                              void* d_out, int out_size) {
    const float* hidden   = (const float*)d_in[0];
    const float* supports = (const float*)d_in[1];
    const float* memory   = (const float*)d_in[3];
    const float* nv1      = (const float*)d_in[4];
    const float* nv2      = (const float*)d_in[5];
    const float* wih      = (const float*)d_in[6];
    const float* whh      = (const float*)d_in[7];
    const float* bih      = (const float*)d_in[8];
    const float* bhh      = (const float*)d_in[9];
    const float* sentw    = (const float*)d_in[10];
    const float* gamma    = (const float*)d_in[11];
    const float* beta     = (const float*)d_in[12];
    const float* gw       = (const float*)d_in[13];
    const float* gb       = (const float*)d_in[14];
    const float* outw     = (const float*)d_in[15];
    const float* outb     = (const float*)d_in[16];
    float* dout = (float*)d_out;

    void* pv;
    float *p_keysw, *p_base, *p_h, *p_prev, *p_bnsum, *p_bnsq;
    float4 *p_Kf4, *p_Vf4;
    cudaGetSymbolAddress(&pv, d_keysw); p_keysw = (float*)pv;
    cudaGetSymbolAddress(&pv, d_base);  p_base  = (float*)pv;
    cudaGetSymbolAddress(&pv, d_h);     p_h     = (float*)pv;
    cudaGetSymbolAddress(&pv, d_prev);  p_prev  = (float*)pv;
    cudaGetSymbolAddress(&pv, d_bnsum); p_bnsum = (float*)pv;
    cudaGetSymbolAddress(&pv, d_bnsq);  p_bnsq  = (float*)pv;
    cudaGetSymbolAddress(&pv, d_Kf4);   p_Kf4   = (float4*)pv;
    cudaGetSymbolAddress(&pv, d_Vf4);   p_Vf4   = (float4*)pv;

    const int SMEM_MM   = 17408*4;                       // 69632
    const int SMEM_EIN  = 13056*4;                       // 52224
    const int SMEM_ATTN = 15008*4;                       // 60032
    const int SMEM_GRU  = (2048 + 64*193 + 32*192)*4;    // 82176
    cudaFuncSetAttribute(k_gru,        cudaFuncAttributeMaxDynamicSharedMemorySize, SMEM_GRU);
    cudaFuncSetAttribute(k_attn,       cudaFuncAttributeMaxDynamicSharedMemorySize, SMEM_ATTN);
    cudaFuncSetAttribute(k_matmul_all, cudaFuncAttributeMaxDynamicSharedMemorySize, SMEM_MM);
    cudaFuncSetAttribute(k_einsum_all, cudaFuncAttributeMaxDynamicSharedMemorySize, SMEM_EIN);

    cudaMemcpyAsync(p_h, hidden, (size_t)BNE*sizeof(float), cudaMemcpyDeviceToDevice, 0);
    cudaMemsetAsync(p_prev, 0, (size_t)NNODE*sizeof(float), 0);
    cudaMemsetAsync(p_bnsum, 0, 2*Nn*sizeof(float), 0);
    cudaMemsetAsync(p_bnsq,  0, 2*Nn*sizeof(float), 0);

    // ---- step-invariant precompute ----
    k_adp<<<Nn, 128>>>(nv1, nv2);
    k_matmul_all<<<dim3(163, 8, 3), 256, SMEM_MM>>>(memory, sentw, gw, gb);
    k_einsum_all<<<dim3(6, 16, 9), 256, SMEM_EIN>>>(supports, 0);
    k_einsum_all<<<dim3(6, 16, 9), 256, SMEM_EIN>>>(supports, 1);
    k_permK<<<dim3(192, 3), 256>>>(memory);
    k_permV<<<dim3(192, 3), 256>>>();

    // ---- sequential scan ----
    for (int st = 0; st < St; st++) {
        k_gru<<<325, 192, SMEM_GRU>>>(wih, whh, bih, bhh);
        for (int hop = 0; hop < NHOP; hop++) {
            int idx = st*NHOP + hop;
            int buf = idx & 1;
            k_attn<<<dim3(11, Bb), 256, SMEM_ATTN>>>(p_Kf4 + (size_t)hop*FRAG4_PER_HOP,
                                                     p_Vf4 + (size_t)hop*FRAG4_PER_HOP,
                                                     p_base + (size_t)hop*BNE,
                                                     p_keysw + (size_t)hop*BNE,
                                                     buf);
            k_apply<<<1300, 256>>>(gamma + hop*Nn, beta + hop*Nn, outw, outb,
                                   dout, st, hop == 2 ? 1 : 0, buf);
        }
    }
}

// round 16
// speedup vs baseline: 1.1225x; 1.0323x over previous
#include <cuda_runtime.h>
#include <math.h>

#define Bb 32
#define Nn 325
#define Ee 64
#define St 12
#define NHOP 3
#define NNODE (Bb*Nn)        // 10400
#define BNE (Bb*Nn*Ee)       // 665600
#define SCALE_INV 0.125f
#define FRAG4_PER_BC 1024    // 4 pairs * 8 k8 * 32 lanes (float4 each)
#define FRAG4_PER_HOP (Bb*6*FRAG4_PER_BC)

// ---------------- scratch (device globals; no allocation allowed) ----------------
__device__ float d_adp[Nn*Nn];
__device__ float d_keysw[NHOP*BNE];
__device__ float d_base [NHOP*BNE];
__device__ float d_t6 [NHOP*6*BNE];
__device__ float d_t3b[NHOP*3*BNE];
__device__ float d_yp [NHOP*3*BNE];
__device__ float4 d_Kf4[NHOP*FRAG4_PER_HOP];
__device__ float4 d_Vf4[NHOP*FRAG4_PER_HOP];
__device__ float d_h[BNE], d_u[BNE], d_opre[BNE];
__device__ float d_prev[NNODE], d_sent[NNODE], d_acc[NNODE];
__device__ float d_bnsum[2][Nn], d_bnsq[2][Nn];

// ---------------- tf32 helpers ----------------
__device__ __forceinline__ void split_tf32(float x, float& hi, float& lo) {
    unsigned h; asm("cvt.rna.tf32.f32 %0, %1;" : "=r"(h) : "f"(x));
    float hf = __uint_as_float(h);
    unsigned l; asm("cvt.rna.tf32.f32 %0, %1;" : "=r"(l) : "f"(x - hf));
    hi = hf; lo = __uint_as_float(l);
}
__device__ __forceinline__ float tf32r(float x) {
    unsigned h; asm("cvt.rna.tf32.f32 %0, %1;" : "=r"(h) : "f"(x));
    return __uint_as_float(h);
}

__device__ __forceinline__ void mma8(float* d,
        float a0, float a1, float a2, float a3, float b0, float b1) {
    asm volatile(
        "mma.sync.aligned.m16n8k8.row.col.f32.tf32.tf32.f32 "
        "{%0,%1,%2,%3},{%4,%5,%6,%7},{%8,%9},{%0,%1,%2,%3};"
        : "+f"(d[0]), "+f"(d[1]), "+f"(d[2]), "+f"(d[3])
        : "r"(__float_as_uint(a0)), "r"(__float_as_uint(a1)),
          "r"(__float_as_uint(a2)), "r"(__float_as_uint(a3)),
          "r"(__float_as_uint(b0)), "r"(__float_as_uint(b1)));
}

__device__ __forceinline__ void mma3(float* d,
        const float* ah, const float* al, float bh0, float bh1, float bl0, float bl1) {
    mma8(d, ah[0], ah[1], ah[2], ah[3], bh0, bh1);
    mma8(d, ah[0], ah[1], ah[2], ah[3], bl0, bl1);
    mma8(d, al[0], al[1], al[2], al[3], bh0, bh1);
}

// ---------------- adaptive adjacency ----------------
__global__ void k_adp(const float* __restrict__ nv1, const float* __restrict__ nv2) {
    __shared__ float nv1s[64];
    __shared__ float vals[Nn];
    __shared__ float red[128];
    int n = blockIdx.x, tid = threadIdx.x;
    if (tid < 64) nv1s[tid] = nv1[n*64 + tid];
    __syncthreads();
    float lmax = -1e30f;
    for (int m = tid; m < Nn; m += 128) {
        const float* p = nv2 + m*64;
        float dot = 0.f;
        #pragma unroll
        for (int k = 0; k < 64; k++) dot += nv1s[k]*p[k];
        float v = fmaxf(dot, 0.f);
        vals[m] = v;
        lmax = fmaxf(lmax, v);
    }
    red[tid] = lmax; __syncthreads();
    for (int s = 64; s > 0; s >>= 1) { if (tid < s) red[tid] = fmaxf(red[tid], red[tid+s]); __syncthreads(); }
    float mx = red[0]; __syncthreads();
    float lsum = 0.f;
    for (int m = tid; m < Nn; m += 128) {
        float e = __expf(vals[m] - mx);
        vals[m] = e; lsum += e;
    }
    red[tid] = lsum; __syncthreads();
    for (int s = 64; s > 0; s >>= 1) { if (tid < s) red[tid] += red[tid+s]; __syncthreads(); }
    float inv = 1.f/red[0];
    for (int m = tid; m < Nn; m += 128) d_adp[n*Nn + m] = vals[m]*inv;
}

// ---------------- all hop projections (full 3xTF32): grid (163, 8, 3) ----------------
__global__ void __launch_bounds__(256) k_matmul_all(const float* __restrict__ mem, const float* __restrict__ sentw,
                             const float* __restrict__ gw, const float* __restrict__ gb) {
    extern __shared__ float sm[];
    float* Xhi = sm;            float* Xlo = sm + 4352;
    float* Whi = sm + 8704;     float* Wlo = sm + 13056;
    int hop = blockIdx.z, y = blockIdx.y;
    const float* Mh  = mem + (size_t)hop*BNE;
    const float* Mh1 = mem + (size_t)(hop+1)*BNE;
    const float* Wh  = gw + (size_t)hop*7*4096;
    const float *X, *W, *bias = nullptr; float* out;
    if (y == 0)      { X = Mh;  W = sentw + (size_t)hop*4096; out = d_keysw + (size_t)hop*BNE; }
    else if (y == 1) { X = Mh1; W = Wh; bias = gb + hop*64;   out = d_base  + (size_t)hop*BNE; }
    else             { X = Mh1; W = Wh + (size_t)(y-1)*4096;  out = d_t6 + ((size_t)hop*6 + (y-2))*BNE; }

    int tid = threadIdx.x;
    int rbase = blockIdx.x*64;
    const int R = NNODE;
    for (int idx = tid; idx < 4096; idx += 256) {
        int k = idx >> 6, n = idx & 63;
        float hi, lo; split_tf32(W[idx], hi, lo);
        Whi[n*68 + k] = hi; Wlo[n*68 + k] = lo;
    }
    for (int idx = tid; idx < 4096; idx += 256) {
        int r = idx >> 6, e = idx & 63;
        int rg = rbase + r;
        float v = (rg < R) ? X[(size_t)rg*64 + e] : 0.f;
        float hi, lo; split_tf32(v, hi, lo);
        Xhi[r*68 + e] = hi; Xlo[r*68 + e] = lo;
    }
    __syncthreads();
    int warp = tid >> 5, lane = tid & 31;
    int wm = warp >> 1, wn = warp & 1;
    int ra = wm*16 + (lane >> 2);
    float acc[4][4] = {};
    #pragma unroll
    for (int k8 = 0; k8 < 8; k8++) {
        int e = k8*8 + (lane & 3);
        float ah[4], al[4];
        ah[0] = Xhi[ra*68 + e];     ah[1] = Xhi[(ra+8)*68 + e];
        ah[2] = Xhi[ra*68 + e + 4]; ah[3] = Xhi[(ra+8)*68 + e + 4];
        al[0] = Xlo[ra*68 + e];     al[1] = Xlo[(ra+8)*68 + e];
        al[2] = Xlo[ra*68 + e + 4]; al[3] = Xlo[(ra+8)*68 + e + 4];
        #pragma unroll
        for (int ns = 0; ns < 4; ns++) {
            int nb = wn*32 + ns*8 + (lane >> 2);
            mma3(acc[ns], ah, al, Whi[nb*68 + e], Whi[nb*68 + e + 4],
                                  Wlo[nb*68 + e], Wlo[nb*68 + e + 4]);
        }
    }
    int r1 = rbase + wm*16 + (lane >> 2);
    #pragma unroll
    for (int ns = 0; ns < 4; ns++) {
        int c = wn*32 + ns*8 + (lane & 3)*2;
        float b0 = bias ? bias[c] : 0.f;
        float b1 = bias ? bias[c+1] : 0.f;
        if (r1 < R) {
            out[(size_t)r1*64 + c]     = acc[ns][0] + b0;
            out[(size_t)r1*64 + c + 1] = acc[ns][1] + b1;
        }
        if (r1 + 8 < R) {
            out[(size_t)(r1+8)*64 + c]     = acc[ns][2] + b0;
            out[(size_t)(r1+8)*64 + c + 1] = acc[ns][3] + b1;
        }
    }
}

// ---------------- einsum (single-MMA tf32 both phases): grid (6, 16, 9) ----------------
// phase 0: t3b = t6a + adj_tf32 @ t6b_tf32
// phase 1: yp  = adj_tf32 @ t3b_tf32
// (B-side lo dropped in both — the whole chain feeds the tf32-truncated V fragments)
__global__ void __launch_bounds__(256) k_einsum_all(const float* __restrict__ supports, int phase) {
    extern __shared__ float sm[];
    float* Ahi = sm;          // 64*68
    float* Bhi = sm + 4352;   // 64*68
    int z = blockIdx.z;
    int hop = z/3, s = z%3;
    const float* adj = (s < 2) ? supports + (size_t)s*Nn*Nn : d_adp;
    const float *Xb, *addb; float* outb_;
    if (phase == 0) {
        Xb   = d_t6 + ((size_t)hop*6 + 2*s + 1)*BNE;
        addb = d_t6 + ((size_t)hop*6 + 2*s)*BNE;
        outb_ = d_t3b + ((size_t)hop*3 + s)*BNE;
    } else {
        Xb   = d_t3b + ((size_t)hop*3 + s)*BNE;
        addb = nullptr;
        outb_ = d_yp + ((size_t)hop*3 + s)*BNE;
    }
    int tid = threadIdx.x;
    int b0 = blockIdx.y*2;
    int ng = blockIdx.x*64;
    int warp = tid >> 5, lane = tid & 31;
    int wm = warp >> 1, wn = warp & 1;
    int ra = wm*16 + (lane >> 2);
    float acc[2][4][4] = {};
    for (int mc = 0; mc < 384; mc += 64) {
        __syncthreads();
        for (int idx = tid; idx < 4096; idx += 256) {
            int i = idx >> 6, j = idx & 63;
            int nr = ng + i, mm = mc + j;
            float v = (nr < Nn && mm < Nn) ? adj[(size_t)nr*Nn + mm] : 0.f;
            Ahi[i*68 + j] = tf32r(v);
        }
        #pragma unroll
        for (int q = 0; q < 2; q++) {
            __syncthreads();
            const float* X = Xb + (size_t)(b0 + q)*Nn*64;
            for (int idx = tid; idx < 4096; idx += 256) {
                int k = idx >> 6, e = idx & 63;
                int mm = mc + k;
                float v = (mm < Nn) ? X[(size_t)mm*64 + e] : 0.f;
                Bhi[e*68 + k] = tf32r(v);
            }
            __syncthreads();
            #pragma unroll
            for (int k8 = 0; k8 < 8; k8++) {
                int m = k8*8 + (lane & 3);
                float a0 = Ahi[ra*68 + m];
                float a1 = Ahi[(ra+8)*68 + m];
                float a2 = Ahi[ra*68 + m + 4];
                float a3 = Ahi[(ra+8)*68 + m + 4];
                #pragma unroll
                for (int ns = 0; ns < 4; ns++) {
                    int nb = wn*32 + ns*8 + (lane >> 2);
                    mma8(acc[q][ns], a0, a1, a2, a3, Bhi[nb*68 + m], Bhi[nb*68 + m + 4]);
                }
            }
        }
    }
    int r1 = ng + wm*16 + (lane >> 2);
    #pragma unroll
    for (int q = 0; q < 2; q++) {
        int b = b0 + q;
        #pragma unroll
        for (int ns = 0; ns < 4; ns++) {
            int e = wn*32 + ns*8 + (lane & 3)*2;
            #pragma unroll
            for (int half = 0; half < 2; half++) {
                int nr = r1 + half*8;
                if (nr < Nn) {
                    size_t g = (size_t)b*Nn*64 + (size_t)nr*64 + e;
                    float v0 = acc[q][ns][half*2], v1 = acc[q][ns][half*2+1];
                    if (addb) { v0 += addb[g]; v1 += addb[g+1]; }
                    outb_[g] = v0; outb_[g+1] = v1;
                }
            }
        }
    }
}

// ---------------- fragment permutes (packed float4: pair of ns groups) ----------------
__global__ void k_permK(const float* __restrict__ mem) {
    int hop = blockIdx.y;
    int b = blockIdx.x / 6, c = blockIdx.x % 6;
    const float* K = mem + (size_t)hop*BNE + (size_t)b*Nn*64;
    float4* out = d_Kf4 + (size_t)hop*FRAG4_PER_HOP + (size_t)(b*6 + c)*FRAG4_PER_BC;
    for (int idx = threadIdx.x; idx < FRAG4_PER_BC; idx += 256) {
        int pair = idx >> 8, k8 = (idx >> 5) & 7, lane = idx & 31;
        int kk0 = c*64 + (pair*2)*8 + (lane >> 2);
        int kk1 = kk0 + 8;
        int e = k8*8 + (lane & 3);
        float x = 0.f, y = 0.f, zz = 0.f, w = 0.f;
        if (kk0 < Nn) { x = K[(size_t)kk0*64 + e]; y = K[(size_t)kk0*64 + e + 4]; }
        if (kk1 < Nn) { zz = K[(size_t)kk1*64 + e]; w = K[(size_t)kk1*64 + e + 4]; }
        out[idx] = make_float4(tf32r(x), tf32r(y), tf32r(zz), tf32r(w));
    }
}

__global__ void k_permV() {
    int hop = blockIdx.y;
    int b = blockIdx.x / 6, c = blockIdx.x % 6;
    const float* Y0 = d_yp + ((size_t)hop*3 + 0)*BNE + (size_t)b*Nn*64;
    const float* Y1 = d_yp + ((size_t)hop*3 + 1)*BNE + (size_t)b*Nn*64;
    const float* Y2 = d_yp + ((size_t)hop*3 + 2)*BNE + (size_t)b*Nn*64;
    float4* out = d_Vf4 + (size_t)hop*FRAG4_PER_HOP + (size_t)(b*6 + c)*FRAG4_PER_BC;
    for (int idx = threadIdx.x; idx < FRAG4_PER_BC; idx += 256) {
        int pair = idx >> 8, k8 = (idx >> 5) & 7, lane = idx & 31;
        int e0 = (pair*2)*8 + (lane >> 2);
        int e1 = e0 + 8;
        int kk = c*64 + k8*8 + (lane & 3);
        float x = 0.f, y = 0.f, zz = 0.f, w = 0.f;
        if (kk < Nn) {
            size_t g = (size_t)kk*64;
            x  = Y0[g + e0] + Y1[g + e0] + Y2[g + e0];
            zz = Y0[g + e1] + Y1[g + e1] + Y2[g + e1];
        }
        if (kk + 4 < Nn) {
            size_t g = (size_t)(kk+4)*64;
            y = Y0[g + e0] + Y1[g + e0] + Y2[g + e0];
            w = Y0[g + e1] + Y1[g + e1] + Y2[g + e1];
        }
        out[idx] = make_float4(tf32r(x), tf32r(y), tf32r(zz), tf32r(w));
    }
}

// ---------------- GRU step: 32 rows/block, 325 blocks, 192 threads ----------------
__global__ void k_gru(const float* __restrict__ wih, const float* __restrict__ whh,
                      const float* __restrict__ bih, const float* __restrict__ bhh) {
    extern __shared__ float sm[];
    float* hs  = sm;                 // 32*64
    float* Wt  = sm + 2048;          // 64*193
    float* ghs = Wt + 64*193;        // 32*192
    int tid = threadIdx.x;           // 192
    int g0 = blockIdx.x*32;
    for (int idx = tid; idx < 192*64; idx += 192) {
        int j = idx >> 6, k = idx & 63;
        Wt[k*193 + j] = whh[idx];
    }
    for (int idx = tid; idx < 2048; idx += 192) hs[idx] = d_h[(size_t)g0*64 + idx];
    __syncthreads();
    float acc[32] = {};
    const float4* hs4 = reinterpret_cast<const float4*>(hs);
    #pragma unroll
    for (int kq = 0; kq < 16; kq++) {
        float w0 = Wt[(4*kq+0)*193 + tid];
        float w1 = Wt[(4*kq+1)*193 + tid];
        float w2 = Wt[(4*kq+2)*193 + tid];
        float w3 = Wt[(4*kq+3)*193 + tid];
        #pragma unroll
        for (int i = 0; i < 32; i++) {
            float4 hv = hs4[i*16 + kq];
            acc[i] += hv.x*w0 + hv.y*w1 + hv.z*w2 + hv.w*w3;
        }
    }
    float bj = bhh[tid];
    #pragma unroll
    for (int i = 0; i < 32; i++) ghs[i*192 + tid] = acc[i] + bj;
    __syncthreads();
    for (int idx = tid; idx < 2048; idx += 192) {
        int i = idx >> 6, e = idx & 63;
        int g = g0 + i;
        float pv  = d_prev[g];
        float gir = pv*wih[e]      + bih[e];
        float giz = pv*wih[64+e]   + bih[64+e];
        float gin = pv*wih[128+e]  + bih[128+e];
        float ghr = ghs[i*192 + e];
        float ghz = ghs[i*192 + 64 + e];
        float ghn = ghs[i*192 + 128 + e];
        float r = 1.f/(1.f + __expf(-(gir+ghr)));
        float z = 1.f/(1.f + __expf(-(giz+ghz)));
        float nv = tanhf(gin + r*ghn);
        float hold = hs[idx];
        float hn = (1.f - z)*nv + z*hold;
        d_h[(size_t)g*64 + e] = hn;
        d_u[(size_t)g*64 + e] = hn;
    }
    if (tid < 32) d_acc[g0 + tid] = 0.f;
}

// ---------------- attention per hop: 32 q-rows/block, grid (11, 32) (R14/R15 exact) ----
__global__ void __launch_bounds__(256)
k_attn(const float4* __restrict__ Kf, const float4* __restrict__ Vf,
       const float* __restrict__ base, const float* __restrict__ ksw, int buf) {
    extern __shared__ float sm[];
    float* Qhi  = sm;
    float* Qlo  = sm + 2176;
    float* Ssm  = sm + 4352;              // 32 x 332
    float* invs = sm + 4352 + 10624;      // 32
    int tid = threadIdx.x;                // 256
    int b = blockIdx.y;
    int q0 = blockIdx.x*32;
    int warp = tid >> 5, lane = tid & 31;
    int wm = warp >> 2, wn = warp & 3;
    const size_t bb = (size_t)b*Nn*64;

    for (int idx = tid; idx < 2048; idx += 256) {
        int r = idx >> 6, e = idx & 63;
        int qg = q0 + r;
        float v = (qg < Nn) ? d_u[bb + (size_t)qg*64 + e] : 0.f;
        float hi, lo; split_tf32(v, hi, lo);
        Qhi[r*68 + e] = hi; Qlo[r*68 + e] = lo;
    }
    #pragma unroll
    for (int r = warp*4; r < warp*4 + 4; r++) {
        int qg = q0 + r;
        if (qg < Nn) {
            const float* up = d_u + bb + (size_t)qg*64;
            const float* kp = ksw + bb + (size_t)qg*64;
            float s = up[lane]*kp[lane] + up[32+lane]*kp[32+lane];
            #pragma unroll
            for (int o = 16; o > 0; o >>= 1) s += __shfl_xor_sync(0xffffffffu, s, o);
            if (lane == 0) d_sent[b*Nn + qg] = s*SCALE_INV;
        }
    }
    __syncthreads();

    int ra = wm*16 + (lane >> 2);
    const float4* Kfb = Kf + (size_t)b*6*FRAG4_PER_BC;

    // ---- pass 1: scores = Q K^T / 8 (2 MMAs, one LDG.128 per k8) ----
    for (int c = 0; c < 6; c++) {
        float acc[2][4] = {};
        const float4* Kfc = Kfb + c*FRAG4_PER_BC;
        #pragma unroll
        for (int k8 = 0; k8 < 8; k8++) {
            int e = k8*8 + (lane & 3);
            float ah0 = Qhi[ra*68 + e],     ah1 = Qhi[(ra+8)*68 + e];
            float ah2 = Qhi[ra*68 + e + 4], ah3 = Qhi[(ra+8)*68 + e + 4];
            float al0 = Qlo[ra*68 + e],     al1 = Qlo[(ra+8)*68 + e];
            float al2 = Qlo[ra*68 + e + 4], al3 = Qlo[(ra+8)*68 + e + 4];
            float4 f = Kfc[wn*256 + k8*32 + lane];
            mma8(acc[0], ah0, ah1, ah2, ah3, f.x, f.y);
            mma8(acc[0], al0, al1, al2, al3, f.x, f.y);
            mma8(acc[1], ah0, ah1, ah2, ah3, f.z, f.w);
            mma8(acc[1], al0, al1, al2, al3, f.z, f.w);
        }
        #pragma unroll
        for (int ns = 0; ns < 2; ns++) {
            int key = c*64 + (wn*2 + ns)*8 + (lane & 3)*2;
            if (key < Nn) {
                Ssm[ra*332 + key]     = acc[ns][0]*SCALE_INV;
                Ssm[(ra+8)*332 + key] = acc[ns][2]*SCALE_INV;
            }
            if (key + 1 < Nn) {
                Ssm[ra*332 + key + 1]     = acc[ns][1]*SCALE_INV;
                Ssm[(ra+8)*332 + key + 1] = acc[ns][3]*SCALE_INV;
            }
        }
    }
    __syncthreads();

    // ---- pass 2: softmax rows (unnormalized exp) ----
    #pragma unroll
    for (int r = warp*4; r < warp*4 + 4; r++) {
        float mx = -1e30f;
        for (int m = lane; m < Nn; m += 32) mx = fmaxf(mx, Ssm[r*332 + m]);
        #pragma unroll
        for (int o = 16; o > 0; o >>= 1) mx = fmaxf(mx, __shfl_xor_sync(0xffffffffu, mx, o));
        float sum = 0.f;
        for (int m = lane; m < Nn; m += 32) {
            float ev = __expf(Ssm[r*332 + m] - mx);
            Ssm[r*332 + m] = ev;
            sum += ev;
        }
        #pragma unroll
        for (int o = 16; o > 0; o >>= 1) sum += __shfl_xor_sync(0xffffffffu, sum, o);
        if (lane == 0) invs[r] = 1.f/sum;
    }
    __syncthreads();

    // ---- pass 3: O = P_tf32 @ V_hi (one LDG.128 serves both ns MMAs) ----
    float oacc[2][4] = {};
    const float4* Vfb = Vf + (size_t)b*6*FRAG4_PER_BC;
    for (int c = 0; c < 6; c++) {
        const float4* Vfc = Vfb + c*FRAG4_PER_BC;
        #pragma unroll
        for (int k8 = 0; k8 < 8; k8++) {
            int m = c*64 + k8*8 + (lane & 3);
            float p0 = (m < Nn)     ? Ssm[ra*332 + m]         : 0.f;
            float p1 = (m < Nn)     ? Ssm[(ra+8)*332 + m]     : 0.f;
            float p2 = (m + 4 < Nn) ? Ssm[ra*332 + m + 4]     : 0.f;
            float p3 = (m + 4 < Nn) ? Ssm[(ra+8)*332 + m + 4] : 0.f;
            float a0 = tf32r(p0), a1 = tf32r(p1), a2 = tf32r(p2), a3 = tf32r(p3);
            float4 f = Vfc[wn*256 + k8*32 + lane];
            mma8(oacc[0], a0, a1, a2, a3, f.x, f.y);
            mma8(oacc[1], a0, a1, a2, a3, f.z, f.w);
        }
    }

    // ---- epilogue: opre = oacc*inv + base; BN partial sums ----
    __syncthreads();
    float* rowsum = Qhi;
    float* rowsq  = Qhi + 32;
    if (tid < 64) Qhi[tid] = 0.f;
    __syncthreads();

    float iv1 = invs[ra], iv2 = invs[ra + 8];
    float s1 = 0.f, q1 = 0.f, s2 = 0.f, q2 = 0.f;
    int qg1 = q0 + ra, qg2 = qg1 + 8;
    #pragma unroll
    for (int ns = 0; ns < 2; ns++) {
        int e = (wn*2 + ns)*8 + (lane & 3)*2;
        if (qg1 < Nn) {
            size_t g = bb + (size_t)qg1*64 + e;
            float v0 = oacc[ns][0]*iv1 + base[g];
            float v1 = oacc[ns][1]*iv1 + base[g+1];
            d_opre[g] = v0; d_opre[g+1] = v1;
            s1 += v0 + v1; q1 += v0*v0 + v1*v1;
        }
        if (qg2 < Nn) {
            size_t g = bb + (size_t)qg2*64 + e;
            float v2 = oacc[ns][2]*iv2 + base[g];
            float v3 = oacc[ns][3]*iv2 + base[g+1];
            d_opre[g] = v2; d_opre[g+1] = v3;
            s2 += v2 + v3; q2 += v2*v2 + v3*v3;
        }
    }
    #pragma unroll
    for (int o = 1; o < 4; o <<= 1) {
        s1 += __shfl_xor_sync(0xffffffffu, s1, o);
        q1 += __shfl_xor_sync(0xffffffffu, q1, o);
        s2 += __shfl_xor_sync(0xffffffffu, s2, o);
        q2 += __shfl_xor_sync(0xffffffffu, q2, o);
    }
    if ((lane & 3) == 0) {
        atomicAdd(&rowsum[ra], s1);     atomicAdd(&rowsq[ra], q1);
        atomicAdd(&rowsum[ra + 8], s2); atomicAdd(&rowsq[ra + 8], q2);
    }
    __syncthreads();
    if (tid < 32) {
        int qg = q0 + tid;
        if (qg < Nn) {
            atomicAdd(&d_bnsum[buf][qg], rowsum[tid]);
            atomicAdd(&d_bnsq[buf][qg],  rowsq[tid]);
        }
    }
}

// ---------------- BN apply + u update + sentinel-weighted output accum ----------------
__global__ void k_apply(const float* __restrict__ gamma, const float* __restrict__ beta,
                        const float* __restrict__ outw, const float* __restrict__ outb,
                        float* __restrict__ dout, int step, int lasthop, int buf) {
    int lane = threadIdx.x & 31;
    int g = blockIdx.x*8 + (threadIdx.x >> 5);
    if (blockIdx.x == 0) {
        for (int i = threadIdx.x; i < Nn; i += 256) {
            d_bnsum[buf^1][i] = 0.f;
            d_bnsq[buf^1][i]  = 0.f;
        }
    }
    if (g >= NNODE) return;
    int b = g / Nn, n = g % Nn;
    float mu = d_bnsum[buf][n]*(1.f/2048.f);
    float var = d_bnsq[buf][n]*(1.f/2048.f) - mu*mu;
    float rs = rsqrtf(var + 1e-5f);
    float gm = gamma[n]*rs, bt = beta[n];
    float v1 = (d_opre[(size_t)g*64 + lane]      - mu)*gm + bt;
    float v2 = (d_opre[(size_t)g*64 + 32 + lane] - mu)*gm + bt;
    d_u[(size_t)g*64 + lane]      += v1;
    d_u[(size_t)g*64 + 32 + lane] += v2;
    float dv = v1*outw[lane] + v2*outw[32 + lane];
    #pragma unroll
    for (int o = 16; o > 0; o >>= 1) dv += __shfl_xor_sync(0xffffffffu, dv, o);
    if (lane == 0) {
        float a = d_acc[g] + d_sent[g]*dv;
        d_acc[g] = a;
        if (lasthop) {
            float val = a + outb[0];
            dout[(size_t)b*St*Nn + (size_t)step*Nn + n] = val;
            d_prev[g] = val;
        }
    }
}

// ---------------- host orchestration ----------------
extern "C" void kernel_launch(void* const* d_in, const int* in_sizes, int n_in,
                              void* d_out, int out_size) {
    const float* hidden   = (const float*)d_in[0];
    const float* supports = (const float*)d_in[1];
    const float* memory   = (const float*)d_in[3];
    const float* nv1      = (const float*)d_in[4];
    const float* nv2      = (const float*)d_in[5];
    const float* wih      = (const float*)d_in[6];
    const float* whh      = (const float*)d_in[7];
    const float* bih      = (const float*)d_in[8];
    const float* bhh      = (const float*)d_in[9];
    const float* sentw    = (const float*)d_in[10];
    const float* gamma    = (const float*)d_in[11];
    const float* beta     = (const float*)d_in[12];
    const float* gw       = (const float*)d_in[13];
    const float* gb       = (const float*)d_in[14];
    const float* outw     = (const float*)d_in[15];
    const float* outb     = (const float*)d_in[16];
    float* dout = (float*)d_out;

    void* pv;
    float *p_keysw, *p_base, *p_h, *p_prev, *p_bnsum, *p_bnsq;
    float4 *p_Kf4, *p_Vf4;
    cudaGetSymbolAddress(&pv, d_keysw); p_keysw = (float*)pv;
    cudaGetSymbolAddress(&pv, d_base);  p_base  = (float*)pv;
    cudaGetSymbolAddress(&pv, d_h);     p_h     = (float*)pv;
    cudaGetSymbolAddress(&pv, d_prev);  p_prev  = (float*)pv;
    cudaGetSymbolAddress(&pv, d_bnsum); p_bnsum = (float*)pv;
    cudaGetSymbolAddress(&pv, d_bnsq);  p_bnsq  = (float*)pv;
    cudaGetSymbolAddress(&pv, d_Kf4);   p_Kf4   = (float4*)pv;
    cudaGetSymbolAddress(&pv, d_Vf4);   p_Vf4   = (float4*)pv;

    const int SMEM_MM   = 17408*4;                       // 69632
    const int SMEM_EIN  = 8704*4;                        // 34816 (single-MMA einsum)
    const int SMEM_ATTN = 15008*4;                       // 60032
    const int SMEM_GRU  = (2048 + 64*193 + 32*192)*4;    // 82176
    cudaFuncSetAttribute(k_gru,        cudaFuncAttributeMaxDynamicSharedMemorySize, SMEM_GRU);
    cudaFuncSetAttribute(k_attn,       cudaFuncAttributeMaxDynamicSharedMemorySize, SMEM_ATTN);
    cudaFuncSetAttribute(k_matmul_all, cudaFuncAttributeMaxDynamicSharedMemorySize, SMEM_MM);
    cudaFuncSetAttribute(k_einsum_all, cudaFuncAttributeMaxDynamicSharedMemorySize, SMEM_EIN);

    cudaMemcpyAsync(p_h, hidden, (size_t)BNE*sizeof(float), cudaMemcpyDeviceToDevice, 0);
    cudaMemsetAsync(p_prev, 0, (size_t)NNODE*sizeof(float), 0);
    cudaMemsetAsync(p_bnsum, 0, 2*Nn*sizeof(float), 0);
    cudaMemsetAsync(p_bnsq,  0, 2*Nn*sizeof(float), 0);

    // ---- step-invariant precompute ----
    k_adp<<<Nn, 128>>>(nv1, nv2);
    k_matmul_all<<<dim3(163, 8, 3), 256, SMEM_MM>>>(memory, sentw, gw, gb);
    k_einsum_all<<<dim3(6, 16, 9), 256, SMEM_EIN>>>(supports, 0);
    k_einsum_all<<<dim3(6, 16, 9), 256, SMEM_EIN>>>(supports, 1);
    k_permK<<<dim3(192, 3), 256>>>(memory);
    k_permV<<<dim3(192, 3), 256>>>();

    // ---- sequential scan ----
    for (int st = 0; st < St; st++) {
        k_gru<<<325, 192, SMEM_GRU>>>(wih, whh, bih, bhh);
        for (int hop = 0; hop < NHOP; hop++) {
            int idx = st*NHOP + hop;
            int buf = idx & 1;
            k_attn<<<dim3(11, Bb), 256, SMEM_ATTN>>>(p_Kf4 + (size_t)hop*FRAG4_PER_HOP,
                                                     p_Vf4 + (size_t)hop*FRAG4_PER_HOP,
                                                     p_base + (size_t)hop*BNE,
                                                     p_keysw + (size_t)hop*BNE,
                                                     buf);
            k_apply<<<1300, 256>>>(gamma + hop*Nn, beta + hop*Nn, outw, outb,
                                   dout, st, hop == 2 ? 1 : 0, buf);
        }
    }
}

// round 17
// speedup vs baseline: 1.1942x; 1.0639x over previous
#include <cuda_runtime.h>
#include <math.h>

#define Bb 32
#define Nn 325
#define Ee 64
#define St 12
#define NHOP 3
#define NNODE (Bb*Nn)        // 10400
#define BNE (Bb*Nn*Ee)       // 665600
#define SCALE_INV 0.125f
#define FRAG4_PER_BC 1024    // 4 pairs * 8 k8 * 32 lanes (float4 each)
#define FRAG4_PER_HOP (Bb*6*FRAG4_PER_BC)

// ---------------- scratch (device globals; no allocation allowed) ----------------
__device__ float d_adp[Nn*Nn];
__device__ float d_keysw[NHOP*BNE];
__device__ float d_base [NHOP*BNE];
__device__ float d_t6 [NHOP*6*BNE];
__device__ float d_t3b[NHOP*3*BNE];
__device__ float d_yp [NHOP*3*BNE];
__device__ float4 d_Kf4[NHOP*FRAG4_PER_HOP];
__device__ float4 d_Vf4[NHOP*FRAG4_PER_HOP];
__device__ float d_h[BNE], d_u[BNE], d_opre[BNE];
__device__ float d_prev[NNODE], d_sent[NNODE], d_acc[NNODE];
__device__ float d_bnsum[2][Nn], d_bnsq[2][Nn];

// ---------------- tf32 helpers ----------------
__device__ __forceinline__ void split_tf32(float x, float& hi, float& lo) {
    unsigned h; asm("cvt.rna.tf32.f32 %0, %1;" : "=r"(h) : "f"(x));
    float hf = __uint_as_float(h);
    unsigned l; asm("cvt.rna.tf32.f32 %0, %1;" : "=r"(l) : "f"(x - hf));
    hi = hf; lo = __uint_as_float(l);
}
__device__ __forceinline__ float tf32r(float x) {
    unsigned h; asm("cvt.rna.tf32.f32 %0, %1;" : "=r"(h) : "f"(x));
    return __uint_as_float(h);
}

__device__ __forceinline__ void mma8(float* d,
        float a0, float a1, float a2, float a3, float b0, float b1) {
    asm volatile(
        "mma.sync.aligned.m16n8k8.row.col.f32.tf32.tf32.f32 "
        "{%0,%1,%2,%3},{%4,%5,%6,%7},{%8,%9},{%0,%1,%2,%3};"
        : "+f"(d[0]), "+f"(d[1]), "+f"(d[2]), "+f"(d[3])
        : "r"(__float_as_uint(a0)), "r"(__float_as_uint(a1)),
          "r"(__float_as_uint(a2)), "r"(__float_as_uint(a3)),
          "r"(__float_as_uint(b0)), "r"(__float_as_uint(b1)));
}

__device__ __forceinline__ void mma3(float* d,
        const float* ah, const float* al, float bh0, float bh1, float bl0, float bl1) {
    mma8(d, ah[0], ah[1], ah[2], ah[3], bh0, bh1);
    mma8(d, ah[0], ah[1], ah[2], ah[3], bl0, bl1);
    mma8(d, al[0], al[1], al[2], al[3], bh0, bh1);
}

// ---------------- adaptive adjacency ----------------
__global__ void k_adp(const float* __restrict__ nv1, const float* __restrict__ nv2) {
    __shared__ float nv1s[64];
    __shared__ float vals[Nn];
    __shared__ float red[128];
    int n = blockIdx.x, tid = threadIdx.x;
    if (tid < 64) nv1s[tid] = nv1[n*64 + tid];
    __syncthreads();
    float lmax = -1e30f;
    for (int m = tid; m < Nn; m += 128) {
        const float* p = nv2 + m*64;
        float dot = 0.f;
        #pragma unroll
        for (int k = 0; k < 64; k++) dot += nv1s[k]*p[k];
        float v = fmaxf(dot, 0.f);
        vals[m] = v;
        lmax = fmaxf(lmax, v);
    }
    red[tid] = lmax; __syncthreads();
    for (int s = 64; s > 0; s >>= 1) { if (tid < s) red[tid] = fmaxf(red[tid], red[tid+s]); __syncthreads(); }
    float mx = red[0]; __syncthreads();
    float lsum = 0.f;
    for (int m = tid; m < Nn; m += 128) {
        float e = __expf(vals[m] - mx);
        vals[m] = e; lsum += e;
    }
    red[tid] = lsum; __syncthreads();
    for (int s = 64; s > 0; s >>= 1) { if (tid < s) red[tid] += red[tid+s]; __syncthreads(); }
    float inv = 1.f/red[0];
    for (int m = tid; m < Nn; m += 128) d_adp[n*Nn + m] = vals[m]*inv;
}

// ---------------- all hop projections (full 3xTF32): grid (163, 8, 3) ----------------
__global__ void __launch_bounds__(256) k_matmul_all(const float* __restrict__ mem, const float* __restrict__ sentw,
                             const float* __restrict__ gw, const float* __restrict__ gb) {
    extern __shared__ float sm[];
    float* Xhi = sm;            float* Xlo = sm + 4352;
    float* Whi = sm + 8704;     float* Wlo = sm + 13056;
    int hop = blockIdx.z, y = blockIdx.y;
    const float* Mh  = mem + (size_t)hop*BNE;
    const float* Mh1 = mem + (size_t)(hop+1)*BNE;
    const float* Wh  = gw + (size_t)hop*7*4096;
    const float *X, *W, *bias = nullptr; float* out;
    if (y == 0)      { X = Mh;  W = sentw + (size_t)hop*4096; out = d_keysw + (size_t)hop*BNE; }
    else if (y == 1) { X = Mh1; W = Wh; bias = gb + hop*64;   out = d_base  + (size_t)hop*BNE; }
    else             { X = Mh1; W = Wh + (size_t)(y-1)*4096;  out = d_t6 + ((size_t)hop*6 + (y-2))*BNE; }

    int tid = threadIdx.x;
    int rbase = blockIdx.x*64;
    const int R = NNODE;
    // W staging (float4 along n)
    for (int idx4 = tid; idx4 < 1024; idx4 += 256) {
        int k = idx4 >> 4, n4 = idx4 & 15;
        float4 f = *reinterpret_cast<const float4*>(W + (size_t)k*64 + n4*4);
        float hi, lo;
        split_tf32(f.x, hi, lo); Whi[(4*n4+0)*68 + k] = hi; Wlo[(4*n4+0)*68 + k] = lo;
        split_tf32(f.y, hi, lo); Whi[(4*n4+1)*68 + k] = hi; Wlo[(4*n4+1)*68 + k] = lo;
        split_tf32(f.z, hi, lo); Whi[(4*n4+2)*68 + k] = hi; Wlo[(4*n4+2)*68 + k] = lo;
        split_tf32(f.w, hi, lo); Whi[(4*n4+3)*68 + k] = hi; Wlo[(4*n4+3)*68 + k] = lo;
    }
    // X staging (float4 along e)
    for (int idx4 = tid; idx4 < 1024; idx4 += 256) {
        int r = idx4 >> 4, e4 = idx4 & 15;
        int rg = rbase + r;
        float4 f = make_float4(0.f, 0.f, 0.f, 0.f);
        if (rg < R) f = *reinterpret_cast<const float4*>(X + (size_t)rg*64 + e4*4);
        float hi, lo;
        split_tf32(f.x, hi, lo); Xhi[r*68 + 4*e4 + 0] = hi; Xlo[r*68 + 4*e4 + 0] = lo;
        split_tf32(f.y, hi, lo); Xhi[r*68 + 4*e4 + 1] = hi; Xlo[r*68 + 4*e4 + 1] = lo;
        split_tf32(f.z, hi, lo); Xhi[r*68 + 4*e4 + 2] = hi; Xlo[r*68 + 4*e4 + 2] = lo;
        split_tf32(f.w, hi, lo); Xhi[r*68 + 4*e4 + 3] = hi; Xlo[r*68 + 4*e4 + 3] = lo;
    }
    __syncthreads();
    int warp = tid >> 5, lane = tid & 31;
    int wm = warp >> 1, wn = warp & 1;
    int ra = wm*16 + (lane >> 2);
    float acc[4][4] = {};
    #pragma unroll
    for (int k8 = 0; k8 < 8; k8++) {
        int e = k8*8 + (lane & 3);
        float ah[4], al[4];
        ah[0] = Xhi[ra*68 + e];     ah[1] = Xhi[(ra+8)*68 + e];
        ah[2] = Xhi[ra*68 + e + 4]; ah[3] = Xhi[(ra+8)*68 + e + 4];
        al[0] = Xlo[ra*68 + e];     al[1] = Xlo[(ra+8)*68 + e];
        al[2] = Xlo[ra*68 + e + 4]; al[3] = Xlo[(ra+8)*68 + e + 4];
        #pragma unroll
        for (int ns = 0; ns < 4; ns++) {
            int nb = wn*32 + ns*8 + (lane >> 2);
            mma3(acc[ns], ah, al, Whi[nb*68 + e], Whi[nb*68 + e + 4],
                                  Wlo[nb*68 + e], Wlo[nb*68 + e + 4]);
        }
    }
    int r1 = rbase + wm*16 + (lane >> 2);
    #pragma unroll
    for (int ns = 0; ns < 4; ns++) {
        int c = wn*32 + ns*8 + (lane & 3)*2;
        float b0 = bias ? bias[c] : 0.f;
        float b1 = bias ? bias[c+1] : 0.f;
        if (r1 < R) {
            out[(size_t)r1*64 + c]     = acc[ns][0] + b0;
            out[(size_t)r1*64 + c + 1] = acc[ns][1] + b1;
        }
        if (r1 + 8 < R) {
            out[(size_t)(r1+8)*64 + c]     = acc[ns][2] + b0;
            out[(size_t)(r1+8)*64 + c + 1] = acc[ns][3] + b1;
        }
    }
}

// ---------------- einsum (single-MMA tf32 both phases): grid (6, 16, 9) ----------------
__global__ void __launch_bounds__(256) k_einsum_all(const float* __restrict__ supports, int phase) {
    extern __shared__ float sm[];
    float* Ahi = sm;          // 64*68
    float* Bhi = sm + 4352;   // 64*68
    int z = blockIdx.z;
    int hop = z/3, s = z%3;
    const float* adj = (s < 2) ? supports + (size_t)s*Nn*Nn : d_adp;
    const float *Xb, *addb; float* outb_;
    if (phase == 0) {
        Xb   = d_t6 + ((size_t)hop*6 + 2*s + 1)*BNE;
        addb = d_t6 + ((size_t)hop*6 + 2*s)*BNE;
        outb_ = d_t3b + ((size_t)hop*3 + s)*BNE;
    } else {
        Xb   = d_t3b + ((size_t)hop*3 + s)*BNE;
        addb = nullptr;
        outb_ = d_yp + ((size_t)hop*3 + s)*BNE;
    }
    int tid = threadIdx.x;
    int b0 = blockIdx.y*2;
    int ng = blockIdx.x*64;
    int warp = tid >> 5, lane = tid & 31;
    int wm = warp >> 1, wn = warp & 1;
    int ra = wm*16 + (lane >> 2);
    float acc[2][4][4] = {};
    for (int mc = 0; mc < 384; mc += 64) {
        __syncthreads();
        for (int idx = tid; idx < 4096; idx += 256) {
            int i = idx >> 6, j = idx & 63;
            int nr = ng + i, mm = mc + j;
            float v = (nr < Nn && mm < Nn) ? adj[(size_t)nr*Nn + mm] : 0.f;
            Ahi[i*68 + j] = tf32r(v);
        }
        #pragma unroll
        for (int q = 0; q < 2; q++) {
            __syncthreads();
            const float* X = Xb + (size_t)(b0 + q)*Nn*64;
            // B staging (float4 along e)
            for (int idx4 = tid; idx4 < 1024; idx4 += 256) {
                int k = idx4 >> 4, e4 = idx4 & 15;
                int mm = mc + k;
                float4 f = make_float4(0.f, 0.f, 0.f, 0.f);
                if (mm < Nn) f = *reinterpret_cast<const float4*>(X + (size_t)mm*64 + e4*4);
                Bhi[(4*e4+0)*68 + k] = tf32r(f.x);
                Bhi[(4*e4+1)*68 + k] = tf32r(f.y);
                Bhi[(4*e4+2)*68 + k] = tf32r(f.z);
                Bhi[(4*e4+3)*68 + k] = tf32r(f.w);
            }
            __syncthreads();
            #pragma unroll
            for (int k8 = 0; k8 < 8; k8++) {
                int m = k8*8 + (lane & 3);
                float a0 = Ahi[ra*68 + m];
                float a1 = Ahi[(ra+8)*68 + m];
                float a2 = Ahi[ra*68 + m + 4];
                float a3 = Ahi[(ra+8)*68 + m + 4];
                #pragma unroll
                for (int ns = 0; ns < 4; ns++) {
                    int nb = wn*32 + ns*8 + (lane >> 2);
                    mma8(acc[q][ns], a0, a1, a2, a3, Bhi[nb*68 + m], Bhi[nb*68 + m + 4]);
                }
            }
        }
    }
    int r1 = ng + wm*16 + (lane >> 2);
    #pragma unroll
    for (int q = 0; q < 2; q++) {
        int b = b0 + q;
        #pragma unroll
        for (int ns = 0; ns < 4; ns++) {
            int e = wn*32 + ns*8 + (lane & 3)*2;
            #pragma unroll
            for (int half = 0; half < 2; half++) {
                int nr = r1 + half*8;
                if (nr < Nn) {
                    size_t g = (size_t)b*Nn*64 + (size_t)nr*64 + e;
                    float v0 = acc[q][ns][half*2], v1 = acc[q][ns][half*2+1];
                    if (addb) { v0 += addb[g]; v1 += addb[g+1]; }
                    outb_[g] = v0; outb_[g+1] = v1;
                }
            }
        }
    }
}

// ---------------- fragment permutes (packed float4: pair of ns groups) ----------------
__global__ void k_permK(const float* __restrict__ mem) {
    int hop = blockIdx.y;
    int b = blockIdx.x / 6, c = blockIdx.x % 6;
    const float* K = mem + (size_t)hop*BNE + (size_t)b*Nn*64;
    float4* out = d_Kf4 + (size_t)hop*FRAG4_PER_HOP + (size_t)(b*6 + c)*FRAG4_PER_BC;
    for (int idx = threadIdx.x; idx < FRAG4_PER_BC; idx += 256) {
        int pair = idx >> 8, k8 = (idx >> 5) & 7, lane = idx & 31;
        int kk0 = c*64 + (pair*2)*8 + (lane >> 2);
        int kk1 = kk0 + 8;
        int e = k8*8 + (lane & 3);
        float x = 0.f, y = 0.f, zz = 0.f, w = 0.f;
        if (kk0 < Nn) { x = K[(size_t)kk0*64 + e]; y = K[(size_t)kk0*64 + e + 4]; }
        if (kk1 < Nn) { zz = K[(size_t)kk1*64 + e]; w = K[(size_t)kk1*64 + e + 4]; }
        out[idx] = make_float4(tf32r(x), tf32r(y), tf32r(zz), tf32r(w));
    }
}

__global__ void k_permV() {
    int hop = blockIdx.y;
    int b = blockIdx.x / 6, c = blockIdx.x % 6;
    const float* Y0 = d_yp + ((size_t)hop*3 + 0)*BNE + (size_t)b*Nn*64;
    const float* Y1 = d_yp + ((size_t)hop*3 + 1)*BNE + (size_t)b*Nn*64;
    const float* Y2 = d_yp + ((size_t)hop*3 + 2)*BNE + (size_t)b*Nn*64;
    float4* out = d_Vf4 + (size_t)hop*FRAG4_PER_HOP + (size_t)(b*6 + c)*FRAG4_PER_BC;
    for (int idx = threadIdx.x; idx < FRAG4_PER_BC; idx += 256) {
        int pair = idx >> 8, k8 = (idx >> 5) & 7, lane = idx & 31;
        int e0 = (pair*2)*8 + (lane >> 2);
        int e1 = e0 + 8;
        int kk = c*64 + k8*8 + (lane & 3);
        float x = 0.f, y = 0.f, zz = 0.f, w = 0.f;
        if (kk < Nn) {
            size_t g = (size_t)kk*64;
            x  = Y0[g + e0] + Y1[g + e0] + Y2[g + e0];
            zz = Y0[g + e1] + Y1[g + e1] + Y2[g + e1];
        }
        if (kk + 4 < Nn) {
            size_t g = (size_t)(kk+4)*64;
            y = Y0[g + e0] + Y1[g + e0] + Y2[g + e0];
            w = Y0[g + e1] + Y1[g + e1] + Y2[g + e1];
        }
        out[idx] = make_float4(tf32r(x), tf32r(y), tf32r(zz), tf32r(w));
    }
}

// ---------------- GRU step: 32 rows/block, 325 blocks, 192 threads ----------------
__global__ void k_gru(const float* __restrict__ wih, const float* __restrict__ whh,
                      const float* __restrict__ bih, const float* __restrict__ bhh) {
    extern __shared__ float sm[];
    float* hs  = sm;                 // 32*64
    float* Wt  = sm + 2048;          // 64*193
    float* ghs = Wt + 64*193;        // 32*192
    int tid = threadIdx.x;           // 192
    int g0 = blockIdx.x*32;
    // Wt staging (float4 along k)
    for (int idx4 = tid; idx4 < 3072; idx4 += 192) {
        int j = idx4 >> 4, k4 = idx4 & 15;
        float4 f = *reinterpret_cast<const float4*>(whh + (size_t)j*64 + k4*4);
        Wt[(4*k4+0)*193 + j] = f.x;
        Wt[(4*k4+1)*193 + j] = f.y;
        Wt[(4*k4+2)*193 + j] = f.z;
        Wt[(4*k4+3)*193 + j] = f.w;
    }
    // hs staging (contiguous float4 copy)
    {
        const float4* src = reinterpret_cast<const float4*>(d_h + (size_t)g0*64);
        float4* dst = reinterpret_cast<float4*>(hs);
        for (int idx4 = tid; idx4 < 512; idx4 += 192) dst[idx4] = src[idx4];
    }
    __syncthreads();
    float acc[32] = {};
    const float4* hs4 = reinterpret_cast<const float4*>(hs);
    #pragma unroll
    for (int kq = 0; kq < 16; kq++) {
        float w0 = Wt[(4*kq+0)*193 + tid];
        float w1 = Wt[(4*kq+1)*193 + tid];
        float w2 = Wt[(4*kq+2)*193 + tid];
        float w3 = Wt[(4*kq+3)*193 + tid];
        #pragma unroll
        for (int i = 0; i < 32; i++) {
            float4 hv = hs4[i*16 + kq];
            acc[i] += hv.x*w0 + hv.y*w1 + hv.z*w2 + hv.w*w3;
        }
    }
    float bj = bhh[tid];
    #pragma unroll
    for (int i = 0; i < 32; i++) ghs[i*192 + tid] = acc[i] + bj;
    __syncthreads();
    for (int idx = tid; idx < 2048; idx += 192) {
        int i = idx >> 6, e = idx & 63;
        int g = g0 + i;
        float pv  = d_prev[g];
        float gir = pv*wih[e]      + bih[e];
        float giz = pv*wih[64+e]   + bih[64+e];
        float gin = pv*wih[128+e]  + bih[128+e];
        float ghr = ghs[i*192 + e];
        float ghz = ghs[i*192 + 64 + e];
        float ghn = ghs[i*192 + 128 + e];
        float r = 1.f/(1.f + __expf(-(gir+ghr)));
        float z = 1.f/(1.f + __expf(-(giz+ghz)));
        float nv = tanhf(gin + r*ghn);
        float hold = hs[idx];
        float hn = (1.f - z)*nv + z*hold;
        d_h[(size_t)g*64 + e] = hn;
        d_u[(size_t)g*64 + e] = hn;
    }
    if (tid < 32) d_acc[g0 + tid] = 0.f;
}

// ---------------- attention per hop: 32 q-rows/block, grid (11, 32) ----------------
__global__ void __launch_bounds__(256)
k_attn(const float4* __restrict__ Kf, const float4* __restrict__ Vf,
       const float* __restrict__ base, const float* __restrict__ ksw, int buf) {
    extern __shared__ float sm[];
    float* Qhi  = sm;
    float* Qlo  = sm + 2176;
    float* Ssm  = sm + 4352;              // 32 x 332
    float* invs = sm + 4352 + 10624;      // 32
    int tid = threadIdx.x;                // 256
    int b = blockIdx.y;
    int q0 = blockIdx.x*32;
    int warp = tid >> 5, lane = tid & 31;
    int wm = warp >> 2, wn = warp & 3;
    const size_t bb = (size_t)b*Nn*64;

    // Q staging (float4 along e)
    for (int idx4 = tid; idx4 < 512; idx4 += 256) {
        int r = idx4 >> 4, e4 = idx4 & 15;
        int qg = q0 + r;
        float4 f = make_float4(0.f, 0.f, 0.f, 0.f);
        if (qg < Nn) f = *reinterpret_cast<const float4*>(d_u + bb + (size_t)qg*64 + e4*4);
        float hi, lo;
        split_tf32(f.x, hi, lo); Qhi[r*68 + 4*e4 + 0] = hi; Qlo[r*68 + 4*e4 + 0] = lo;
        split_tf32(f.y, hi, lo); Qhi[r*68 + 4*e4 + 1] = hi; Qlo[r*68 + 4*e4 + 1] = lo;
        split_tf32(f.z, hi, lo); Qhi[r*68 + 4*e4 + 2] = hi; Qlo[r*68 + 4*e4 + 2] = lo;
        split_tf32(f.w, hi, lo); Qhi[r*68 + 4*e4 + 3] = hi; Qlo[r*68 + 4*e4 + 3] = lo;
    }
    #pragma unroll
    for (int r = warp*4; r < warp*4 + 4; r++) {
        int qg = q0 + r;
        if (qg < Nn) {
            const float* up = d_u + bb + (size_t)qg*64;
            const float* kp = ksw + bb + (size_t)qg*64;
            float s = up[lane]*kp[lane] + up[32+lane]*kp[32+lane];
            #pragma unroll
            for (int o = 16; o > 0; o >>= 1) s += __shfl_xor_sync(0xffffffffu, s, o);
            if (lane == 0) d_sent[b*Nn + qg] = s*SCALE_INV;
        }
    }
    __syncthreads();

    int ra = wm*16 + (lane >> 2);
    const float4* Kfb = Kf + (size_t)b*6*FRAG4_PER_BC;

    // ---- pass 1: scores = Q K^T / 8 (2 MMAs, one LDG.128 per k8) ----
    for (int c = 0; c < 6; c++) {
        float acc[2][4] = {};
        const float4* Kfc = Kfb + c*FRAG4_PER_BC;
        #pragma unroll
        for (int k8 = 0; k8 < 8; k8++) {
            int e = k8*8 + (lane & 3);
            float ah0 = Qhi[ra*68 + e],     ah1 = Qhi[(ra+8)*68 + e];
            float ah2 = Qhi[ra*68 + e + 4], ah3 = Qhi[(ra+8)*68 + e + 4];
            float al0 = Qlo[ra*68 + e],     al1 = Qlo[(ra+8)*68 + e];
            float al2 = Qlo[ra*68 + e + 4], al3 = Qlo[(ra+8)*68 + e + 4];
            float4 f = Kfc[wn*256 + k8*32 + lane];
            mma8(acc[0], ah0, ah1, ah2, ah3, f.x, f.y);
            mma8(acc[0], al0, al1, al2, al3, f.x, f.y);
            mma8(acc[1], ah0, ah1, ah2, ah3, f.z, f.w);
            mma8(acc[1], al0, al1, al2, al3, f.z, f.w);
        }
        #pragma unroll
        for (int ns = 0; ns < 2; ns++) {
            int key = c*64 + (wn*2 + ns)*8 + (lane & 3)*2;
            if (key < Nn) {
                Ssm[ra*332 + key]     = acc[ns][0]*SCALE_INV;
                Ssm[(ra+8)*332 + key] = acc[ns][2]*SCALE_INV;
            }
            if (key + 1 < Nn) {
                Ssm[ra*332 + key + 1]     = acc[ns][1]*SCALE_INV;
                Ssm[(ra+8)*332 + key + 1] = acc[ns][3]*SCALE_INV;
            }
        }
    }
    __syncthreads();

    // ---- pass 2: softmax rows (unnormalized exp) ----
    #pragma unroll
    for (int r = warp*4; r < warp*4 + 4; r++) {
        float mx = -1e30f;
        for (int m = lane; m < Nn; m += 32) mx = fmaxf(mx, Ssm[r*332 + m]);
        #pragma unroll
        for (int o = 16; o > 0; o >>= 1) mx = fmaxf(mx, __shfl_xor_sync(0xffffffffu, mx, o));
        float sum = 0.f;
        for (int m = lane; m < Nn; m += 32) {
            float ev = __expf(Ssm[r*332 + m] - mx);
            Ssm[r*332 + m] = ev;
            sum += ev;
        }
        #pragma unroll
        for (int o = 16; o > 0; o >>= 1) sum += __shfl_xor_sync(0xffffffffu, sum, o);
        if (lane == 0) invs[r] = 1.f/sum;
    }
    __syncthreads();

    // ---- pass 3: O = P_tf32 @ V_hi (one LDG.128 serves both ns MMAs) ----
    float oacc[2][4] = {};
    const float4* Vfb = Vf + (size_t)b*6*FRAG4_PER_BC;
    for (int c = 0; c < 6; c++) {
        const float4* Vfc = Vfb + c*FRAG4_PER_BC;
        #pragma unroll
        for (int k8 = 0; k8 < 8; k8++) {
            int m = c*64 + k8*8 + (lane & 3);
            float p0 = (m < Nn)     ? Ssm[ra*332 + m]         : 0.f;
            float p1 = (m < Nn)     ? Ssm[(ra+8)*332 + m]     : 0.f;
            float p2 = (m + 4 < Nn) ? Ssm[ra*332 + m + 4]     : 0.f;
            float p3 = (m + 4 < Nn) ? Ssm[(ra+8)*332 + m + 4] : 0.f;
            float a0 = tf32r(p0), a1 = tf32r(p1), a2 = tf32r(p2), a3 = tf32r(p3);
            float4 f = Vfc[wn*256 + k8*32 + lane];
            mma8(oacc[0], a0, a1, a2, a3, f.x, f.y);
            mma8(oacc[1], a0, a1, a2, a3, f.z, f.w);
        }
    }

    // ---- epilogue: opre = oacc*inv + base; BN partial sums ----
    __syncthreads();
    float* rowsum = Qhi;
    float* rowsq  = Qhi + 32;
    if (tid < 64) Qhi[tid] = 0.f;
    __syncthreads();

    float iv1 = invs[ra], iv2 = invs[ra + 8];
    float s1 = 0.f, q1 = 0.f, s2 = 0.f, q2 = 0.f;
    int qg1 = q0 + ra, qg2 = qg1 + 8;
    #pragma unroll
    for (int ns = 0; ns < 2; ns++) {
        int e = (wn*2 + ns)*8 + (lane & 3)*2;
        if (qg1 < Nn) {
            size_t g = bb + (size_t)qg1*64 + e;
            float v0 = oacc[ns][0]*iv1 + base[g];
            float v1 = oacc[ns][1]*iv1 + base[g+1];
            d_opre[g] = v0; d_opre[g+1] = v1;
            s1 += v0 + v1; q1 += v0*v0 + v1*v1;
        }
        if (qg2 < Nn) {
            size_t g = bb + (size_t)qg2*64 + e;
            float v2 = oacc[ns][2]*iv2 + base[g];
            float v3 = oacc[ns][3]*iv2 + base[g+1];
            d_opre[g] = v2; d_opre[g+1] = v3;
            s2 += v2 + v3; q2 += v2*v2 + v3*v3;
        }
    }
    #pragma unroll
    for (int o = 1; o < 4; o <<= 1) {
        s1 += __shfl_xor_sync(0xffffffffu, s1, o);
        q1 += __shfl_xor_sync(0xffffffffu, q1, o);
        s2 += __shfl_xor_sync(0xffffffffu, s2, o);
        q2 += __shfl_xor_sync(0xffffffffu, q2, o);
    }
    if ((lane & 3) == 0) {
        atomicAdd(&rowsum[ra], s1);     atomicAdd(&rowsq[ra], q1);
        atomicAdd(&rowsum[ra + 8], s2); atomicAdd(&rowsq[ra + 8], q2);
    }
    __syncthreads();
    if (tid < 32) {
        int qg = q0 + tid;
        if (qg < Nn) {
            atomicAdd(&d_bnsum[buf][qg], rowsum[tid]);
            atomicAdd(&d_bnsq[buf][qg],  rowsq[tid]);
        }
    }
}

// ---------------- BN apply + u update + sentinel-weighted output accum ----------------
__global__ void k_apply(const float* __restrict__ gamma, const float* __restrict__ beta,
                        const float* __restrict__ outw, const float* __restrict__ outb,
                        float* __restrict__ dout, int step, int lasthop, int buf) {
    int lane = threadIdx.x & 31;
    int g = blockIdx.x*8 + (threadIdx.x >> 5);
    if (blockIdx.x == 0) {
        for (int i = threadIdx.x; i < Nn; i += 256) {
            d_bnsum[buf^1][i] = 0.f;
            d_bnsq[buf^1][i]  = 0.f;
        }
    }
    if (g >= NNODE) return;
    int b = g / Nn, n = g % Nn;
    float mu = d_bnsum[buf][n]*(1.f/2048.f);
    float var = d_bnsq[buf][n]*(1.f/2048.f) - mu*mu;
    float rs = rsqrtf(var + 1e-5f);
    float gm = gamma[n]*rs, bt = beta[n];
    float v1 = (d_opre[(size_t)g*64 + lane]      - mu)*gm + bt;
    float v2 = (d_opre[(size_t)g*64 + 32 + lane] - mu)*gm + bt;
    d_u[(size_t)g*64 + lane]      += v1;
    d_u[(size_t)g*64 + 32 + lane] += v2;
    float dv = v1*outw[lane] + v2*outw[32 + lane];
    #pragma unroll
    for (int o = 16; o > 0; o >>= 1) dv += __shfl_xor_sync(0xffffffffu, dv, o);
    if (lane == 0) {
        float a = d_acc[g] + d_sent[g]*dv;
        d_acc[g] = a;
        if (lasthop) {
            float val = a + outb[0];
            dout[(size_t)b*St*Nn + (size_t)step*Nn + n] = val;
            d_prev[g] = val;
        }
    }
}

// ---------------- host orchestration ----------------
extern "C" void kernel_launch(void* const* d_in, const int* in_sizes, int n_in,
                              void* d_out, int out_size) {
    const float* hidden   = (const float*)d_in[0];
    const float* supports = (const float*)d_in[1];
    const float* memory   = (const float*)d_in[3];
    const float* nv1      = (const float*)d_in[4];
    const float* nv2      = (const float*)d_in[5];
    const float* wih      = (const float*)d_in[6];
    const float* whh      = (const float*)d_in[7];
    const float* bih      = (const float*)d_in[8];
    const float* bhh      = (const float*)d_in[9];
    const float* sentw    = (const float*)d_in[10];
    const float* gamma    = (const float*)d_in[11];
    const float* beta     = (const float*)d_in[12];
    const float* gw       = (const float*)d_in[13];
    const float* gb       = (const float*)d_in[14];
    const float* outw     = (const float*)d_in[15];
    const float* outb     = (const float*)d_in[16];
    float* dout = (float*)d_out;

    void* pv;
    float *p_keysw, *p_base, *p_h, *p_prev, *p_bnsum, *p_bnsq;
    float4 *p_Kf4, *p_Vf4;
    cudaGetSymbolAddress(&pv, d_keysw); p_keysw = (float*)pv;
    cudaGetSymbolAddress(&pv, d_base);  p_base  = (float*)pv;
    cudaGetSymbolAddress(&pv, d_h);     p_h     = (float*)pv;
    cudaGetSymbolAddress(&pv, d_prev);  p_prev  = (float*)pv;
    cudaGetSymbolAddress(&pv, d_bnsum); p_bnsum = (float*)pv;
    cudaGetSymbolAddress(&pv, d_bnsq);  p_bnsq  = (float*)pv;
    cudaGetSymbolAddress(&pv, d_Kf4);   p_Kf4   = (float4*)pv;
    cudaGetSymbolAddress(&pv, d_Vf4);   p_Vf4   = (float4*)pv;

    const int SMEM_MM   = 17408*4;                       // 69632
    const int SMEM_EIN  = 8704*4;                        // 34816
    const int SMEM_ATTN = 15008*4;                       // 60032
    const int SMEM_GRU  = (2048 + 64*193 + 32*192)*4;    // 82176
    cudaFuncSetAttribute(k_gru,        cudaFuncAttributeMaxDynamicSharedMemorySize, SMEM_GRU);
    cudaFuncSetAttribute(k_attn,       cudaFuncAttributeMaxDynamicSharedMemorySize, SMEM_ATTN);
    cudaFuncSetAttribute(k_matmul_all, cudaFuncAttributeMaxDynamicSharedMemorySize, SMEM_MM);
    cudaFuncSetAttribute(k_einsum_all, cudaFuncAttributeMaxDynamicSharedMemorySize, SMEM_EIN);

    cudaMemcpyAsync(p_h, hidden, (size_t)BNE*sizeof(float), cudaMemcpyDeviceToDevice, 0);
    cudaMemsetAsync(p_prev, 0, (size_t)NNODE*sizeof(float), 0);
    cudaMemsetAsync(p_bnsum, 0, 2*Nn*sizeof(float), 0);
    cudaMemsetAsync(p_bnsq,  0, 2*Nn*sizeof(float), 0);

    // ---- step-invariant precompute ----
    k_adp<<<Nn, 128>>>(nv1, nv2);
    k_matmul_all<<<dim3(163, 8, 3), 256, SMEM_MM>>>(memory, sentw, gw, gb);
    k_einsum_all<<<dim3(6, 16, 9), 256, SMEM_EIN>>>(supports, 0);
    k_einsum_all<<<dim3(6, 16, 9), 256, SMEM_EIN>>>(supports, 1);
    k_permK<<<dim3(192, 3), 256>>>(memory);
    k_permV<<<dim3(192, 3), 256>>>();

    // ---- sequential scan ----
    for (int st = 0; st < St; st++) {
        k_gru<<<325, 192, SMEM_GRU>>>(wih, whh, bih, bhh);
        for (int hop = 0; hop < NHOP; hop++) {
            int idx = st*NHOP + hop;
            int buf = idx & 1;
            k_attn<<<dim3(11, Bb), 256, SMEM_ATTN>>>(p_Kf4 + (size_t)hop*FRAG4_PER_HOP,
                                                     p_Vf4 + (size_t)hop*FRAG4_PER_HOP,
                                                     p_base + (size_t)hop*BNE,
                                                     p_keysw + (size_t)hop*BNE,
                                                     buf);
            k_apply<<<1300, 256>>>(gamma + hop*Nn, beta + hop*Nn, outw, outb,
                                   dout, st, hop == 2 ? 1 : 0, buf);
        }
    }
}